// round 8
// baseline (speedup 1.0000x reference)
#include <cuda_runtime.h>
#include <math.h>
#include <cstdint>

#define NB 16
#define NC 256
#define NNP 2304   // N = 48*48 pixels
#define ND 32      // d = C/8
#define NR 320     // packed qkv rows: 32 q + 32 k + 256 v
#define NKC 72     // k-chunks of 32 in NNP
#define NIT 18     // 128-pixel i-tiles in NNP

// ---- scratch (static device globals; no allocation at runtime) ----
__device__ float g_W[NR * NC];
__device__ float g_bias[NR];
__device__ float g_qkv[(size_t)NB * NR * NNP];         // 47 MB
__device__ float g_energy[(size_t)NB * NNP * NNP];     // 340 MB, E^T[j][i]
__device__ float g_P[(size_t)NB * NNP * NNP];          // 340 MB, fragment-ordered probs (tf32 bits)
__device__ float g_Vf[(size_t)NB * NKC * 8192];        // 38 MB, fragment-ordered v (tf32 bits)

__device__ __forceinline__ uint32_t f2tf32(float f) {
    uint32_t r; asm("cvt.rna.tf32.f32 %0, %1;" : "=r"(r) : "f"(f)); return r;
}
__device__ __forceinline__ void mma_tf32(float* c, const uint32_t* a, const uint32_t* b) {
    asm volatile(
        "mma.sync.aligned.m16n8k8.row.col.f32.tf32.tf32.f32 "
        "{%0,%1,%2,%3}, {%4,%5,%6,%7}, {%8,%9}, {%0,%1,%2,%3};"
        : "+f"(c[0]), "+f"(c[1]), "+f"(c[2]), "+f"(c[3])
        : "r"(a[0]), "r"(a[1]), "r"(a[2]), "r"(a[3]), "r"(b[0]), "r"(b[1]));
}
__device__ __forceinline__ void cp_async16(void* smem_dst, const void* gmem_src) {
    uint32_t sa = (uint32_t)__cvta_generic_to_shared(smem_dst);
    asm volatile("cp.async.cg.shared.global [%0], [%1], 16;" :: "r"(sa), "l"(gmem_src));
}
#define CP_COMMIT() asm volatile("cp.async.commit_group;" ::: "memory")
#define CP_WAIT(n)  asm volatile("cp.async.wait_group %0;" :: "n"(n) : "memory")

// ---------------------------------------------------------------------------
// K0: pack weights + biases
// ---------------------------------------------------------------------------
__global__ void pack_w_kernel(const float* __restrict__ Wq, const float* __restrict__ bq,
                              const float* __restrict__ Wk, const float* __restrict__ bk,
                              const float* __restrict__ Wv, const float* __restrict__ bv) {
    int idx = blockIdx.x * blockDim.x + threadIdx.x;
    if (idx < NR * NC) {
        int r = idx / NC, c = idx - r * NC;
        float v;
        if (r < ND)          v = Wq[r * NC + c];
        else if (r < 2 * ND) v = Wk[(r - ND) * NC + c];
        else                 v = Wv[(r - 2 * ND) * NC + c];
        g_W[idx] = v;
    }
    if (idx < NR) {
        float v;
        if (idx < ND)          v = bq[idx];
        else if (idx < 2 * ND) v = bk[idx - ND];
        else                   v = bv[idx - 2 * ND];
        g_bias[idx] = v;
    }
}

// ---------------------------------------------------------------------------
// K1: qkv projection GEMM (fp32 SIMT)
// ---------------------------------------------------------------------------
__global__ __launch_bounds__(256) void qkv_gemm_kernel(const float* __restrict__ x) {
    int b = blockIdx.z;
    int m0 = blockIdx.y * 64;
    int n0 = blockIdx.x * 64;
    const float* A  = g_W;
    const float* Bm = x + (size_t)b * NC * NNP;
    float* Cm = g_qkv + (size_t)b * NR * NNP;

    __shared__ float As[16][64];
    __shared__ float Bs[16][64];
    int tid = threadIdx.x;
    int tx = tid & 15, ty = tid >> 4;
    float acc[4][4] = {};

    for (int k0 = 0; k0 < NC; k0 += 16) {
        int ar = tid >> 2, ac = (tid & 3) * 4;
        float4 av = *(const float4*)(A + (size_t)(m0 + ar) * NC + k0 + ac);
        As[ac + 0][ar] = av.x; As[ac + 1][ar] = av.y;
        As[ac + 2][ar] = av.z; As[ac + 3][ar] = av.w;
        int br = tid >> 4, bc = (tid & 15) * 4;
        *(float4*)&Bs[br][bc] = *(const float4*)(Bm + (size_t)(k0 + br) * NNP + n0 + bc);
        __syncthreads();
#pragma unroll
        for (int kk = 0; kk < 16; kk++) {
            float a[4], bb[4];
            *(float4*)a  = *(const float4*)&As[kk][ty * 4];
            *(float4*)bb = *(const float4*)&Bs[kk][tx * 4];
#pragma unroll
            for (int i = 0; i < 4; i++)
#pragma unroll
                for (int j = 0; j < 4; j++)
                    acc[i][j] += a[i] * bb[j];
        }
        __syncthreads();
    }
#pragma unroll
    for (int i = 0; i < 4; i++) {
        int m = m0 + ty * 4 + i;
        float bias = g_bias[m];
        float4 o;
        o.x = acc[i][0] + bias; o.y = acc[i][1] + bias;
        o.z = acc[i][2] + bias; o.w = acc[i][3] + bias;
        *(float4*)(Cm + (size_t)m * NNP + n0 + tx * 4) = o;
    }
}

// ---------------------------------------------------------------------------
// K2: E^T[b][j][i] = k . q  (fp32 SIMT, exact for softmax)
// ---------------------------------------------------------------------------
__global__ __launch_bounds__(256) void energy_gemm_kernel() {
    int b = blockIdx.z;
    int j0 = blockIdx.y * 128;
    int i0 = blockIdx.x * 128;
    const float* A  = g_qkv + (size_t)b * NR * NNP + (size_t)ND * NNP;
    const float* Bq = g_qkv + (size_t)b * NR * NNP;
    float* Cm = g_energy + (size_t)b * NNP * NNP;

    __shared__ float As[8][128];
    __shared__ float Bs[8][128];
    int tid = threadIdx.x;
    int tx = tid & 15, ty = tid >> 4;
    float acc[8][8] = {};

    for (int k0 = 0; k0 < ND; k0 += 8) {
        int lr = tid >> 5, lc = (tid & 31) * 4;
        *(float4*)&As[lr][lc] = *(const float4*)(A  + (size_t)(k0 + lr) * NNP + j0 + lc);
        *(float4*)&Bs[lr][lc] = *(const float4*)(Bq + (size_t)(k0 + lr) * NNP + i0 + lc);
        __syncthreads();
#pragma unroll
        for (int kk = 0; kk < 8; kk++) {
            float a[8], bb[8];
            *(float4*)&a[0]  = *(const float4*)&As[kk][ty * 4];
            *(float4*)&a[4]  = *(const float4*)&As[kk][64 + ty * 4];
            *(float4*)&bb[0] = *(const float4*)&Bs[kk][tx * 4];
            *(float4*)&bb[4] = *(const float4*)&Bs[kk][64 + tx * 4];
#pragma unroll
            for (int i = 0; i < 8; i++)
#pragma unroll
                for (int j = 0; j < 8; j++)
                    acc[i][j] += a[i] * bb[j];
        }
        __syncthreads();
    }
#pragma unroll
    for (int ih = 0; ih < 2; ih++)
#pragma unroll
        for (int i = 0; i < 4; i++) {
            int j = j0 + ih * 64 + ty * 4 + i;
#pragma unroll
            for (int jh = 0; jh < 2; jh++) {
                float4 o;
                o.x = acc[ih * 4 + i][jh * 4 + 0];
                o.y = acc[ih * 4 + i][jh * 4 + 1];
                o.z = acc[ih * 4 + i][jh * 4 + 2];
                o.w = acc[ih * 4 + i][jh * 4 + 3];
                *(float4*)(Cm + (size_t)j * NNP + i0 + jh * 64 + tx * 4) = o;
            }
        }
}

// ---------------------------------------------------------------------------
// K3 (fused): stats + pack.  Block per (kc, b): 32 j-rows.
// pass1: per-row max + logsumexp (warp per row, 4 rows/warp), L in smem.
// pass2: re-read rows (L2-resident; occupancy capped at 2 CTAs/SM via smem),
//        exp + tf32 + fragment permute, write g_P.
// ---------------------------------------------------------------------------
#define SP_SMEM 98304   // 96KB request -> 2 CTAs/SM -> wave set ~84MB fits L2

__global__ __launch_bounds__(256) void stats_pack_kernel() {
    extern __shared__ float dsm[];
    float* sp  = dsm;          // 4096 floats pack staging
    float* Lsm = dsm + 4096;   // 32 floats
    int kc = blockIdx.x, b = blockIdx.y;
    const float* Eb = g_energy + (size_t)b * NNP * NNP + (size_t)(kc * 32) * NNP;
    int t = threadIdx.x, lane = t & 31, w = t >> 5;

    // ---- pass1: L[r] = max + log(sum exp) over the 2304-long row ----
#pragma unroll
    for (int rr = 0; rr < 4; rr++) {
        int r = w + rr * 8;
        const float* row = Eb + (size_t)r * NNP;
        float m = -1e30f;
#pragma unroll
        for (int u = 0; u < 18; u++) {
            float4 v = *(const float4*)(row + (u * 32 + lane) * 4);
            m = fmaxf(m, fmaxf(fmaxf(v.x, v.y), fmaxf(v.z, v.w)));
        }
#pragma unroll
        for (int s = 16; s; s >>= 1) m = fmaxf(m, __shfl_xor_sync(0xFFFFFFFFu, m, s));
        float sum = 0.f;
#pragma unroll
        for (int u = 0; u < 18; u++) {
            float4 v = *(const float4*)(row + (u * 32 + lane) * 4);
            sum += __expf(v.x - m) + __expf(v.y - m) + __expf(v.z - m) + __expf(v.w - m);
        }
#pragma unroll
        for (int s = 16; s; s >>= 1) sum += __shfl_xor_sync(0xFFFFFFFFu, sum, s);
        if (lane == 0) Lsm[r] = m + __logf(sum);
    }
    __syncthreads();

    // ---- pass2: pack 18 i-tiles of (32 j x 128 i) ----
    int k  = ((t >> 6) << 3) | (t & 7);   // 0..31, lanes span k&7
    int fc = (t >> 3) & 7;
    float L = Lsm[k];
    int ks = k >> 3;
    int klow = (k & 3) * 2 + ((k >> 2) & 1);
    const float* rowk = Eb + (size_t)k * NNP;
    for (int itile = 0; itile < NIT; itile++) {
        const float* rowi = rowk + itile * 128;
#pragma unroll
        for (int u = 0; u < 4; u++) {
            int c4 = fc + u * 8;
            float4 e = *(const float4*)(rowi + c4 * 4);
            int n = c4 * 4;
            int b0 = ((n >> 3) * 4 + ks) * 64 + (n & 7) * 8 + klow;
            sp[b0 +  0] = __uint_as_float(f2tf32(__expf(e.x - L)));
            sp[b0 +  8] = __uint_as_float(f2tf32(__expf(e.y - L)));
            sp[b0 + 16] = __uint_as_float(f2tf32(__expf(e.z - L)));
            sp[b0 + 24] = __uint_as_float(f2tf32(__expf(e.w - L)));
        }
        __syncthreads();
        float4* dst = (float4*)(g_P + (((size_t)b * NIT + itile) * NKC + kc) * 4096);
        const float4* src = (const float4*)sp;
#pragma unroll
        for (int u = 0; u < 4; u++) dst[t + u * 256] = src[t + u * 256];
        __syncthreads();
    }
}

// ---------------------------------------------------------------------------
// K1b: vf_pack — v as tf32 bits in mma A-fragment order (MT=256 tile).
// ---------------------------------------------------------------------------
__global__ __launch_bounds__(256) void vf_pack_kernel() {
    int kc = blockIdx.x;     // 0..71
    int b  = blockIdx.y;
    const float* V = g_qkv + (size_t)b * NR * NNP + (size_t)(2 * ND) * NNP;
    __shared__ float sa[8192];
    int t = threadIdx.x;     // = channel row m
    const float* row = V + (size_t)t * NNP + kc * 32;
    int mt = t >> 4, mr = t & 15;
    int mpart = (mr & 7) * 4;
    int madd = (mr >> 3) & 1;
#pragma unroll
    for (int u = 0; u < 8; u++) {
        float4 v = *(const float4*)(row + u * 4);
        int ks = u >> 1;
        int base = ((mt * 4 + ks) * 32 + mpart) * 4 + madd + (u & 1) * 2;
        sa[base +  0] = __uint_as_float(f2tf32(v.x));
        sa[base +  4] = __uint_as_float(f2tf32(v.y));
        sa[base +  8] = __uint_as_float(f2tf32(v.z));
        sa[base + 12] = __uint_as_float(f2tf32(v.w));
    }
    __syncthreads();
    float4* dst = (float4*)(g_Vf + ((size_t)b * NKC + kc) * 8192);
    const float4* src = (const float4*)sa;
#pragma unroll
    for (int u = 0; u < 8; u++) dst[t + u * 256] = src[t + u * 256];
}

// ---------------------------------------------------------------------------
// K4: out = gamma * (V @ P) + x  via mma.sync tf32.
// CTA: M=256 (all channels) x N=128 pixels; K chunks of 32.
// 3-stage cp.async ring, ONE __syncthreads per iter, prefetch before compute.
// ---------------------------------------------------------------------------
#define ITERS NKC
#define S_STAGE 12288                   // floats per stage: A 8192 + B 4096
#define S_TOTAL3 (3 * S_STAGE * 4)      // 144 KB

__device__ __forceinline__ void og_prefetch(float* smem, const float* Vb, const float* Pb,
                                            int it, int slot, int tid) {
    float* sA = smem + slot * S_STAGE;
    float* sB = sA + 8192;
    const float4* srcA = (const float4*)(Vb + (size_t)it * 8192);
    const float4* srcB = (const float4*)(Pb + (size_t)it * 4096);
#pragma unroll
    for (int u = 0; u < 8; u++)
        cp_async16((float4*)sA + tid + u * 256, srcA + tid + u * 256);
#pragma unroll
    for (int u = 0; u < 4; u++)
        cp_async16((float4*)sB + tid + u * 256, srcB + tid + u * 256);
    CP_COMMIT();
}

__global__ __launch_bounds__(256, 1) void out_gemm_tc_kernel(const float* __restrict__ x,
                                                             const float* __restrict__ gamma,
                                                             float* __restrict__ out) {
    extern __shared__ float smem[];
    const int tid = threadIdx.x;
    const int lane = tid & 31;
    const int wid = tid >> 5;
    const int warp_m = wid & 3;        // 4 m-tiles of 64 rows
    const int warp_n = wid >> 2;       // 2 n-tiles of 64 cols

    const int itile = blockIdx.x;      // 0..17
    const int b = blockIdx.y;

    const float* Vb = g_Vf + (size_t)b * NKC * 8192;
    const float* Pb = g_P + (((size_t)b * NIT + itile) * NKC) * 4096;

    float acc[4][8][4];
#pragma unroll
    for (int i = 0; i < 4; i++)
#pragma unroll
        for (int j = 0; j < 8; j++)
#pragma unroll
            for (int r = 0; r < 4; r++) acc[i][j][r] = 0.f;

    og_prefetch(smem, Vb, Pb, 0, 0, tid);
    og_prefetch(smem, Vb, Pb, 1, 1, tid);

    int slot = 0, nslot = 2;
    for (int it = 0; it < ITERS; it++) {
        if (it < ITERS - 1) { CP_WAIT(1); } else { CP_WAIT(0); }
        __syncthreads();
        if (it + 2 < ITERS) {
            og_prefetch(smem, Vb, Pb, it + 2, nslot, tid);
            if (++nslot == 3) nslot = 0;
        }

        const uint32_t* uA = (const uint32_t*)(smem + slot * S_STAGE);
        const uint32_t* uB = uA + 8192;
        if (++slot == 3) slot = 0;
#pragma unroll
        for (int ks = 0; ks < 4; ks++) {
            uint32_t a[4][4];
            uint32_t bfr[8][2];
#pragma unroll
            for (int i = 0; i < 4; i++) {
                int mt = warp_m * 4 + i;
                uint4 tdat = *(const uint4*)(uA + ((mt * 4 + ks) * 32 + lane) * 4);
                a[i][0] = tdat.x; a[i][1] = tdat.y; a[i][2] = tdat.z; a[i][3] = tdat.w;
            }
#pragma unroll
            for (int j = 0; j < 8; j++) {
                int nt = warp_n * 8 + j;
                uint2 tdat = *(const uint2*)(uB + ((nt * 4 + ks) * 32 + lane) * 2);
                bfr[j][0] = tdat.x; bfr[j][1] = tdat.y;
            }
#pragma unroll
            for (int i = 0; i < 4; i++)
#pragma unroll
                for (int j = 0; j < 8; j++)
                    mma_tf32(acc[i][j], a[i], bfr[j]);
        }
    }

    // ---- epilogue: gamma*acc + x, float2 stores ----
    const float g = gamma[0];
    const float* xb = x + (size_t)b * NC * NNP;
    float* ob = out + (size_t)b * NC * NNP;
    const int gq = lane >> 2, tq = lane & 3;
#pragma unroll
    for (int i = 0; i < 4; i++) {
        int row0 = warp_m * 64 + i * 16 + gq;
#pragma unroll
        for (int j = 0; j < 8; j++) {
            int n = itile * 128 + warp_n * 64 + j * 8 + tq * 2;
            size_t o0 = (size_t)row0 * NNP + n;
            size_t o1 = o0 + (size_t)8 * NNP;
            float2 x0 = *(const float2*)(xb + o0);
            float2 x1 = *(const float2*)(xb + o1);
            float2 r0, r1;
            r0.x = g * acc[i][j][0] + x0.x;
            r0.y = g * acc[i][j][1] + x0.y;
            r1.x = g * acc[i][j][2] + x1.x;
            r1.y = g * acc[i][j][3] + x1.y;
            *(float2*)(ob + o0) = r0;
            *(float2*)(ob + o1) = r1;
        }
    }
}

// ---------------------------------------------------------------------------
extern "C" void kernel_launch(void* const* d_in, const int* in_sizes, int n_in,
                              void* d_out, int out_size) {
    const float* x     = (const float*)d_in[0];
    const float* Wq    = (const float*)d_in[1];
    const float* bq    = (const float*)d_in[2];
    const float* Wk    = (const float*)d_in[3];
    const float* bk    = (const float*)d_in[4];
    const float* Wv    = (const float*)d_in[5];
    const float* bv    = (const float*)d_in[6];
    const float* gamma = (const float*)d_in[7];
    float* out = (float*)d_out;

    pack_w_kernel<<<(NR * NC + 255) / 256, 256>>>(Wq, bq, Wk, bk, Wv, bv);

    dim3 g1(NNP / 64, NR / 64, NB);
    qkv_gemm_kernel<<<g1, 256>>>(x);

    dim3 g2(NNP / 128, NNP / 128, NB);
    energy_gemm_kernel<<<g2, 256>>>();

    dim3 gv(NKC, NB);
    vf_pack_kernel<<<gv, 256>>>();

    cudaFuncSetAttribute(stats_pack_kernel, cudaFuncAttributeMaxDynamicSharedMemorySize, SP_SMEM);
    dim3 gs(NKC, NB);
    stats_pack_kernel<<<gs, 256, SP_SMEM>>>();

    cudaFuncSetAttribute(out_gemm_tc_kernel, cudaFuncAttributeMaxDynamicSharedMemorySize, S_TOTAL3);
    dim3 g4(NIT, NB);
    out_gemm_tc_kernel<<<g4, 256, S_TOTAL3>>>(x, gamma, out);
}

// round 10
// speedup vs baseline: 1.2239x; 1.2239x over previous
#include <cuda_runtime.h>
#include <cuda_fp16.h>
#include <math.h>
#include <cstdint>

#define NB 16
#define NC 256
#define NNP 2304   // N = 48*48 pixels
#define ND 32      // d = C/8
#define NR 320     // packed qkv rows: 32 q + 32 k + 256 v
#define NKC 72     // k-chunks of 32 in NNP
#define NIT 18     // 128-pixel i-tiles in NNP

// ---- scratch (static device globals; no allocation at runtime) ----
__device__ float g_W[NR * NC];
__device__ float g_bias[NR];
__device__ float g_qkv[(size_t)NB * NR * NNP];            // 47 MB
__device__ float g_energy[(size_t)NB * NNP * NNP];        // 340 MB, E^T[j][i]
__device__ float g_L[NB * NNP];                           // M[j] + log S[j]
__device__ uint32_t g_Ph[(size_t)NB * NIT * NKC * 2048];  // 170 MB, fp16 fragment-ordered probs
__device__ uint32_t g_Vfh[(size_t)NB * NKC * 4096];       // 19 MB, fp16 fragment-ordered v

__device__ __forceinline__ uint32_t packh2(float lo, float hi) {
    __half2 h = __floats2half2_rn(lo, hi);
    return *reinterpret_cast<uint32_t*>(&h);
}
__device__ __forceinline__ void mma_f16(float* c, const uint32_t* a, const uint32_t* b) {
    asm volatile(
        "mma.sync.aligned.m16n8k16.row.col.f32.f16.f16.f32 "
        "{%0,%1,%2,%3}, {%4,%5,%6,%7}, {%8,%9}, {%0,%1,%2,%3};"
        : "+f"(c[0]), "+f"(c[1]), "+f"(c[2]), "+f"(c[3])
        : "r"(a[0]), "r"(a[1]), "r"(a[2]), "r"(a[3]), "r"(b[0]), "r"(b[1]));
}
__device__ __forceinline__ void cp_async16(void* smem_dst, const void* gmem_src) {
    uint32_t sa = (uint32_t)__cvta_generic_to_shared(smem_dst);
    asm volatile("cp.async.cg.shared.global [%0], [%1], 16;" :: "r"(sa), "l"(gmem_src));
}
#define CP_COMMIT() asm volatile("cp.async.commit_group;" ::: "memory")
#define CP_WAIT(n)  asm volatile("cp.async.wait_group %0;" :: "n"(n) : "memory")

// ---------------------------------------------------------------------------
// K0: pack weights + biases
// ---------------------------------------------------------------------------
__global__ void pack_w_kernel(const float* __restrict__ Wq, const float* __restrict__ bq,
                              const float* __restrict__ Wk, const float* __restrict__ bk,
                              const float* __restrict__ Wv, const float* __restrict__ bv) {
    int idx = blockIdx.x * blockDim.x + threadIdx.x;
    if (idx < NR * NC) {
        int r = idx / NC, c = idx - r * NC;
        float v;
        if (r < ND)          v = Wq[r * NC + c];
        else if (r < 2 * ND) v = Wk[(r - ND) * NC + c];
        else                 v = Wv[(r - 2 * ND) * NC + c];
        g_W[idx] = v;
    }
    if (idx < NR) {
        float v;
        if (idx < ND)          v = bq[idx];
        else if (idx < 2 * ND) v = bk[idx - ND];
        else                   v = bv[idx - 2 * ND];
        g_bias[idx] = v;
    }
}

// ---------------------------------------------------------------------------
// K1: qkv projection GEMM (fp32 SIMT)
// ---------------------------------------------------------------------------
__global__ __launch_bounds__(256) void qkv_gemm_kernel(const float* __restrict__ x) {
    int b = blockIdx.z;
    int m0 = blockIdx.y * 64;
    int n0 = blockIdx.x * 64;
    const float* A  = g_W;
    const float* Bm = x + (size_t)b * NC * NNP;
    float* Cm = g_qkv + (size_t)b * NR * NNP;

    __shared__ float As[16][64];
    __shared__ float Bs[16][64];
    int tid = threadIdx.x;
    int tx = tid & 15, ty = tid >> 4;
    float acc[4][4] = {};

    for (int k0 = 0; k0 < NC; k0 += 16) {
        int ar = tid >> 2, ac = (tid & 3) * 4;
        float4 av = *(const float4*)(A + (size_t)(m0 + ar) * NC + k0 + ac);
        As[ac + 0][ar] = av.x; As[ac + 1][ar] = av.y;
        As[ac + 2][ar] = av.z; As[ac + 3][ar] = av.w;
        int br = tid >> 4, bc = (tid & 15) * 4;
        *(float4*)&Bs[br][bc] = *(const float4*)(Bm + (size_t)(k0 + br) * NNP + n0 + bc);
        __syncthreads();
#pragma unroll
        for (int kk = 0; kk < 16; kk++) {
            float a[4], bb[4];
            *(float4*)a  = *(const float4*)&As[kk][ty * 4];
            *(float4*)bb = *(const float4*)&Bs[kk][tx * 4];
#pragma unroll
            for (int i = 0; i < 4; i++)
#pragma unroll
                for (int j = 0; j < 4; j++)
                    acc[i][j] += a[i] * bb[j];
        }
        __syncthreads();
    }
#pragma unroll
    for (int i = 0; i < 4; i++) {
        int m = m0 + ty * 4 + i;
        float bias = g_bias[m];
        float4 o;
        o.x = acc[i][0] + bias; o.y = acc[i][1] + bias;
        o.z = acc[i][2] + bias; o.w = acc[i][3] + bias;
        *(float4*)(Cm + (size_t)m * NNP + n0 + tx * 4) = o;
    }
}

// ---------------------------------------------------------------------------
// K2: E^T[b][j][i] = k . q  (fp32 SIMT, exact for softmax)
// ---------------------------------------------------------------------------
__global__ __launch_bounds__(256) void energy_gemm_kernel() {
    int b = blockIdx.z;
    int j0 = blockIdx.y * 128;
    int i0 = blockIdx.x * 128;
    const float* A  = g_qkv + (size_t)b * NR * NNP + (size_t)ND * NNP;
    const float* Bq = g_qkv + (size_t)b * NR * NNP;
    float* Cm = g_energy + (size_t)b * NNP * NNP;

    __shared__ float As[8][128];
    __shared__ float Bs[8][128];
    int tid = threadIdx.x;
    int tx = tid & 15, ty = tid >> 4;
    float acc[8][8] = {};

    for (int k0 = 0; k0 < ND; k0 += 8) {
        int lr = tid >> 5, lc = (tid & 31) * 4;
        *(float4*)&As[lr][lc] = *(const float4*)(A  + (size_t)(k0 + lr) * NNP + j0 + lc);
        *(float4*)&Bs[lr][lc] = *(const float4*)(Bq + (size_t)(k0 + lr) * NNP + i0 + lc);
        __syncthreads();
#pragma unroll
        for (int kk = 0; kk < 8; kk++) {
            float a[8], bb[8];
            *(float4*)&a[0]  = *(const float4*)&As[kk][ty * 4];
            *(float4*)&a[4]  = *(const float4*)&As[kk][64 + ty * 4];
            *(float4*)&bb[0] = *(const float4*)&Bs[kk][tx * 4];
            *(float4*)&bb[4] = *(const float4*)&Bs[kk][64 + tx * 4];
#pragma unroll
            for (int i = 0; i < 8; i++)
#pragma unroll
                for (int j = 0; j < 8; j++)
                    acc[i][j] += a[i] * bb[j];
        }
        __syncthreads();
    }
#pragma unroll
    for (int ih = 0; ih < 2; ih++)
#pragma unroll
        for (int i = 0; i < 4; i++) {
            int j = j0 + ih * 64 + ty * 4 + i;
#pragma unroll
            for (int jh = 0; jh < 2; jh++) {
                float4 o;
                o.x = acc[ih * 4 + i][jh * 4 + 0];
                o.y = acc[ih * 4 + i][jh * 4 + 1];
                o.z = acc[ih * 4 + i][jh * 4 + 2];
                o.w = acc[ih * 4 + i][jh * 4 + 3];
                *(float4*)(Cm + (size_t)j * NNP + i0 + jh * 64 + tx * 4) = o;
            }
        }
}

// ---------------------------------------------------------------------------
// K3: per-key-column stats  L[j] = max_i + log(sum_i exp)   (R7 version)
// ---------------------------------------------------------------------------
__global__ __launch_bounds__(256) void softmax_stats_kernel() {
    int b = blockIdx.y;
    int j = blockIdx.x;
    const float* row = g_energy + (size_t)b * NNP * NNP + (size_t)j * NNP;
    int tid = threadIdx.x;

    float vals[9];
    float m = -1e30f;
#pragma unroll
    for (int u = 0; u < 9; u++) {
        vals[u] = row[tid + u * 256];
        m = fmaxf(m, vals[u]);
    }
    __shared__ float red[256];
    red[tid] = m; __syncthreads();
    for (int s = 128; s > 0; s >>= 1) {
        if (tid < s) red[tid] = fmaxf(red[tid], red[tid + s]);
        __syncthreads();
    }
    m = red[0]; __syncthreads();
    float sum = 0.f;
#pragma unroll
    for (int u = 0; u < 9; u++) sum += __expf(vals[u] - m);
    red[tid] = sum; __syncthreads();
    for (int s = 128; s > 0; s >>= 1) {
        if (tid < s) red[tid] += red[tid + s];
        __syncthreads();
    }
    if (tid == 0) g_L[b * NNP + j] = m + __logf(red[0]);
}

// ---------------------------------------------------------------------------
// K3b: p_pack_h — P = exp(E^T - L) as fp16 pairs in m16n8k16 B-fragment order.
// B(k,n): lane=(n&7)*4+((k>>1)&3), reg=(k>>3)&1, half=k&1, tile nt=n>>3, ks=k>>4.
// Thread: kp = t&15 (k-pair 2kp,2kp+1), nb = t>>4 (8 n's). nt == nb exactly.
// ---------------------------------------------------------------------------
__global__ __launch_bounds__(256) void p_pack_h_kernel() {
    int itile = blockIdx.x;         // 0..17
    int kc = blockIdx.y;            // 0..71
    int b  = blockIdx.z;
    const float* E = g_energy + (size_t)b * NNP * NNP + (size_t)(kc * 32) * NNP + itile * 128;
    const float* Lr = g_L + b * NNP + kc * 32;
    __shared__ uint32_t sp[2048];
    int t = threadIdx.x;
    int kp = t & 15;
    int nb = t >> 4;
    int k0 = kp * 2;
    float L0 = Lr[k0], L1 = Lr[k0 + 1];
    const float* r0 = E + (size_t)k0 * NNP + nb * 8;
    const float* r1 = r0 + NNP;
    float e0[8], e1[8];
    *(float4*)&e0[0] = *(const float4*)r0;  *(float4*)&e0[4] = *(const float4*)(r0 + 4);
    *(float4*)&e1[0] = *(const float4*)r1;  *(float4*)&e1[4] = *(const float4*)(r1 + 4);
    int ks = kp >> 3, rg = (kp >> 2) & 1, kl = kp & 3;
    int base = ((nb * 2 + ks) * 32 + kl) * 2 + rg;
#pragma unroll
    for (int u = 0; u < 8; u++)
        sp[base + u * 8] = packh2(__expf(e0[u] - L0), __expf(e1[u] - L1));
    __syncthreads();
    uint4* dst = (uint4*)(g_Ph + (((size_t)b * NIT + itile) * NKC + kc) * 2048);
    const uint4* src = (const uint4*)sp;
    dst[t] = src[t];
    dst[t + 256] = src[t + 256];
}

// ---------------------------------------------------------------------------
// K1b: vf_pack_h — v as fp16 pairs in m16n8k16 A-fragment order.
// A(m,k): lane=(m&7)*4+((k>>1)&3), reg=((m>>3)&1)+2*((k>>3)&1), half=k&1,
//         tile mt=m>>4, ks=k>>4.
// ---------------------------------------------------------------------------
__global__ __launch_bounds__(256) void vf_pack_h_kernel() {
    int kc = blockIdx.x;     // 0..71
    int b  = blockIdx.y;
    const float* V = g_qkv + (size_t)b * NR * NNP + (size_t)(2 * ND) * NNP;
    __shared__ uint32_t sa[4096];
    int t = threadIdx.x;     // = channel row m
    const float* row = V + (size_t)t * NNP + kc * 32;
    float v[32];
#pragma unroll
    for (int u = 0; u < 8; u++) *(float4*)&v[u * 4] = *(const float4*)(row + u * 4);
    int mt = t >> 4;
    int lanebase = (t & 7) * 4;
    int madd = (t >> 3) & 1;
#pragma unroll
    for (int kp = 0; kp < 16; kp++) {
        uint32_t h = packh2(v[2 * kp], v[2 * kp + 1]);
        int idx = ((mt * 2 + (kp >> 3)) * 32 + lanebase + (kp & 3)) * 4 + madd + 2 * ((kp >> 2) & 1);
        sa[idx] = h;
    }
    __syncthreads();
    uint4* dst = (uint4*)(g_Vfh + ((size_t)b * NKC + kc) * 4096);
    const uint4* src = (const uint4*)sa;
#pragma unroll
    for (int u = 0; u < 4; u++) dst[t + u * 256] = src[t + u * 256];
}

// ---------------------------------------------------------------------------
// K4: out = gamma * (V @ P) + x  via mma.sync fp16 (m16n8k16), f32 accum.
// CTA: M=256 (all channels) x N=128 pixels; K chunks of 32 (2 k-steps of 16).
// 3-stage cp.async ring, one __syncthreads per iter, prefetch before compute.
// ---------------------------------------------------------------------------
#define ITERS NKC
#define S_STAGE 6144                    // uints per stage: A 4096 + B 2048
#define S_TOTAL3 (3 * S_STAGE * 4)      // 72 KB

__device__ __forceinline__ void og_prefetch(uint32_t* smem, const uint32_t* Vb, const uint32_t* Pb,
                                            int it, int slot, int tid) {
    uint32_t* sA = smem + slot * S_STAGE;
    uint32_t* sB = sA + 4096;
    const uint4* srcA = (const uint4*)(Vb + (size_t)it * 4096);
    const uint4* srcB = (const uint4*)(Pb + (size_t)it * 2048);
#pragma unroll
    for (int u = 0; u < 4; u++)
        cp_async16((uint4*)sA + tid + u * 256, srcA + tid + u * 256);
#pragma unroll
    for (int u = 0; u < 2; u++)
        cp_async16((uint4*)sB + tid + u * 256, srcB + tid + u * 256);
    CP_COMMIT();
}

__global__ __launch_bounds__(256, 1) void out_gemm_tc_kernel(const float* __restrict__ x,
                                                             const float* __restrict__ gamma,
                                                             float* __restrict__ out) {
    extern __shared__ uint32_t smem[];
    const int tid = threadIdx.x;
    const int lane = tid & 31;
    const int wid = tid >> 5;
    const int warp_m = wid & 3;        // 4 m-tiles of 64 rows
    const int warp_n = wid >> 2;       // 2 n-tiles of 64 cols

    const int itile = blockIdx.x;      // 0..17
    const int b = blockIdx.y;

    const uint32_t* Vb = g_Vfh + (size_t)b * NKC * 4096;
    const uint32_t* Pb = g_Ph + (((size_t)b * NIT + itile) * NKC) * 2048;

    float acc[4][8][4];
#pragma unroll
    for (int i = 0; i < 4; i++)
#pragma unroll
        for (int j = 0; j < 8; j++)
#pragma unroll
            for (int r = 0; r < 4; r++) acc[i][j][r] = 0.f;

    og_prefetch(smem, Vb, Pb, 0, 0, tid);
    og_prefetch(smem, Vb, Pb, 1, 1, tid);

    int slot = 0, nslot = 2;
    for (int it = 0; it < ITERS; it++) {
        if (it < ITERS - 1) { CP_WAIT(1); } else { CP_WAIT(0); }
        __syncthreads();
        if (it + 2 < ITERS) {
            og_prefetch(smem, Vb, Pb, it + 2, nslot, tid);
            if (++nslot == 3) nslot = 0;
        }

        const uint32_t* uA = smem + slot * S_STAGE;
        const uint32_t* uB = uA + 4096;
        if (++slot == 3) slot = 0;
#pragma unroll
        for (int ks = 0; ks < 2; ks++) {
            uint32_t a[4][4];
            uint32_t bfr[8][2];
#pragma unroll
            for (int i = 0; i < 4; i++) {
                int mt = warp_m * 4 + i;
                uint4 tdat = *(const uint4*)(uA + ((mt * 2 + ks) * 32 + lane) * 4);
                a[i][0] = tdat.x; a[i][1] = tdat.y; a[i][2] = tdat.z; a[i][3] = tdat.w;
            }
#pragma unroll
            for (int j = 0; j < 8; j++) {
                int nt = warp_n * 8 + j;
                uint2 tdat = *(const uint2*)(uB + ((nt * 2 + ks) * 32 + lane) * 2);
                bfr[j][0] = tdat.x; bfr[j][1] = tdat.y;
            }
#pragma unroll
            for (int i = 0; i < 4; i++)
#pragma unroll
                for (int j = 0; j < 8; j++)
                    mma_f16(acc[i][j], a[i], bfr[j]);
        }
    }

    // ---- epilogue: gamma*acc + x, float2 stores ----
    const float g = gamma[0];
    const float* xb = x + (size_t)b * NC * NNP;
    float* ob = out + (size_t)b * NC * NNP;
    const int gq = lane >> 2, tq = lane & 3;
#pragma unroll
    for (int i = 0; i < 4; i++) {
        int row0 = warp_m * 64 + i * 16 + gq;
#pragma unroll
        for (int j = 0; j < 8; j++) {
            int n = itile * 128 + warp_n * 64 + j * 8 + tq * 2;
            size_t o0 = (size_t)row0 * NNP + n;
            size_t o1 = o0 + (size_t)8 * NNP;
            float2 x0 = *(const float2*)(xb + o0);
            float2 x1 = *(const float2*)(xb + o1);
            float2 r0, r1;
            r0.x = g * acc[i][j][0] + x0.x;
            r0.y = g * acc[i][j][1] + x0.y;
            r1.x = g * acc[i][j][2] + x1.x;
            r1.y = g * acc[i][j][3] + x1.y;
            *(float2*)(ob + o0) = r0;
            *(float2*)(ob + o1) = r1;
        }
    }
}

// ---------------------------------------------------------------------------
extern "C" void kernel_launch(void* const* d_in, const int* in_sizes, int n_in,
                              void* d_out, int out_size) {
    const float* x     = (const float*)d_in[0];
    const float* Wq    = (const float*)d_in[1];
    const float* bq    = (const float*)d_in[2];
    const float* Wk    = (const float*)d_in[3];
    const float* bk    = (const float*)d_in[4];
    const float* Wv    = (const float*)d_in[5];
    const float* bv    = (const float*)d_in[6];
    const float* gamma = (const float*)d_in[7];
    float* out = (float*)d_out;

    pack_w_kernel<<<(NR * NC + 255) / 256, 256>>>(Wq, bq, Wk, bk, Wv, bv);

    dim3 g1(NNP / 64, NR / 64, NB);
    qkv_gemm_kernel<<<g1, 256>>>(x);

    dim3 g2(NNP / 128, NNP / 128, NB);
    energy_gemm_kernel<<<g2, 256>>>();

    dim3 g3(NNP, NB);
    softmax_stats_kernel<<<g3, 256>>>();

    dim3 gv(NKC, NB);
    vf_pack_h_kernel<<<gv, 256>>>();

    dim3 gp(NIT, NKC, NB);
    p_pack_h_kernel<<<gp, 256>>>();

    cudaFuncSetAttribute(out_gemm_tc_kernel, cudaFuncAttributeMaxDynamicSharedMemorySize, S_TOTAL3);
    dim3 g4(NIT, NB);
    out_gemm_tc_kernel<<<g4, 256, S_TOTAL3>>>(x, gamma, out);
}

// round 12
// speedup vs baseline: 1.4085x; 1.1508x over previous
#include <cuda_runtime.h>
#include <cuda_fp16.h>
#include <math.h>
#include <cstdint>

#define NB 16
#define NC 256
#define NNP 2304   // N = 48*48 pixels
#define ND 32      // d = C/8
#define NR 320     // packed qkv rows: 32 q + 32 k + 256 v
#define NKC 72     // k-chunks of 32 in NNP
#define NIT 18     // 128-pixel i-tiles in NNP

// ---- scratch (static device globals; no allocation at runtime) ----
__device__ float g_W[NR * NC];
__device__ float g_bias[NR];
__device__ float g_qkv[(size_t)NB * NR * NNP];            // 47 MB
__device__ float g_energy[(size_t)NB * NNP * NNP];        // 340 MB, E^T[j][i]
__device__ float g_L[NB * NNP];                           // M[j] + log S[j]
__device__ uint32_t g_Ph[(size_t)NB * NIT * NKC * 2048];  // 170 MB, fp16 fragment-ordered probs
__device__ uint32_t g_Vfh[(size_t)NB * NKC * 4096];       // 19 MB, fp16 fragment-ordered v
__device__ uint32_t g_Kfh[(size_t)NB * NIT * 2048];       // 2.4 MB, fp16 A-fragment k (per j-tile)
__device__ uint32_t g_Qfh[(size_t)NB * NIT * 2048];       // 2.4 MB, fp16 B-fragment q (per i-tile)

__device__ __forceinline__ uint32_t packh2(float lo, float hi) {
    __half2 h = __floats2half2_rn(lo, hi);
    return *reinterpret_cast<uint32_t*>(&h);
}
__device__ __forceinline__ void mma_f16(float* c, const uint32_t* a, const uint32_t* b) {
    asm volatile(
        "mma.sync.aligned.m16n8k16.row.col.f32.f16.f16.f32 "
        "{%0,%1,%2,%3}, {%4,%5,%6,%7}, {%8,%9}, {%0,%1,%2,%3};"
        : "+f"(c[0]), "+f"(c[1]), "+f"(c[2]), "+f"(c[3])
        : "r"(a[0]), "r"(a[1]), "r"(a[2]), "r"(a[3]), "r"(b[0]), "r"(b[1]));
}
__device__ __forceinline__ void cp_async16(void* smem_dst, const void* gmem_src) {
    uint32_t sa = (uint32_t)__cvta_generic_to_shared(smem_dst);
    asm volatile("cp.async.cg.shared.global [%0], [%1], 16;" :: "r"(sa), "l"(gmem_src));
}
#define CP_COMMIT() asm volatile("cp.async.commit_group;" ::: "memory")
#define CP_WAIT(n)  asm volatile("cp.async.wait_group %0;" :: "n"(n) : "memory")

// ---------------------------------------------------------------------------
// K0: pack weights + biases
// ---------------------------------------------------------------------------
__global__ void pack_w_kernel(const float* __restrict__ Wq, const float* __restrict__ bq,
                              const float* __restrict__ Wk, const float* __restrict__ bk,
                              const float* __restrict__ Wv, const float* __restrict__ bv) {
    int idx = blockIdx.x * blockDim.x + threadIdx.x;
    if (idx < NR * NC) {
        int r = idx / NC, c = idx - r * NC;
        float v;
        if (r < ND)          v = Wq[r * NC + c];
        else if (r < 2 * ND) v = Wk[(r - ND) * NC + c];
        else                 v = Wv[(r - 2 * ND) * NC + c];
        g_W[idx] = v;
    }
    if (idx < NR) {
        float v;
        if (idx < ND)          v = bq[idx];
        else if (idx < 2 * ND) v = bk[idx - ND];
        else                   v = bv[idx - 2 * ND];
        g_bias[idx] = v;
    }
}

// ---------------------------------------------------------------------------
// K1: qkv projection GEMM (fp32 SIMT)
// ---------------------------------------------------------------------------
__global__ __launch_bounds__(256) void qkv_gemm_kernel(const float* __restrict__ x) {
    int b = blockIdx.z;
    int m0 = blockIdx.y * 64;
    int n0 = blockIdx.x * 64;
    const float* A  = g_W;
    const float* Bm = x + (size_t)b * NC * NNP;
    float* Cm = g_qkv + (size_t)b * NR * NNP;

    __shared__ float As[16][64];
    __shared__ float Bs[16][64];
    int tid = threadIdx.x;
    int tx = tid & 15, ty = tid >> 4;
    float acc[4][4] = {};

    for (int k0 = 0; k0 < NC; k0 += 16) {
        int ar = tid >> 2, ac = (tid & 3) * 4;
        float4 av = *(const float4*)(A + (size_t)(m0 + ar) * NC + k0 + ac);
        As[ac + 0][ar] = av.x; As[ac + 1][ar] = av.y;
        As[ac + 2][ar] = av.z; As[ac + 3][ar] = av.w;
        int br = tid >> 4, bc = (tid & 15) * 4;
        *(float4*)&Bs[br][bc] = *(const float4*)(Bm + (size_t)(k0 + br) * NNP + n0 + bc);
        __syncthreads();
#pragma unroll
        for (int kk = 0; kk < 16; kk++) {
            float a[4], bb[4];
            *(float4*)a  = *(const float4*)&As[kk][ty * 4];
            *(float4*)bb = *(const float4*)&Bs[kk][tx * 4];
#pragma unroll
            for (int i = 0; i < 4; i++)
#pragma unroll
                for (int j = 0; j < 4; j++)
                    acc[i][j] += a[i] * bb[j];
        }
        __syncthreads();
    }
#pragma unroll
    for (int i = 0; i < 4; i++) {
        int m = m0 + ty * 4 + i;
        float bias = g_bias[m];
        float4 o;
        o.x = acc[i][0] + bias; o.y = acc[i][1] + bias;
        o.z = acc[i][2] + bias; o.w = acc[i][3] + bias;
        *(float4*)(Cm + (size_t)m * NNP + n0 + tx * 4) = o;
    }
}

// ---------------------------------------------------------------------------
// K1c: qk_pack — q and k as fp16 pairs in mma fragment order, per 128-tile.
// which=0: k -> A-fragment blocks (for E^T rows j)
// which=1: q -> B-fragment blocks (for E^T cols i)
// ---------------------------------------------------------------------------
__global__ __launch_bounds__(128) void qk_pack_kernel() {
    int tile  = blockIdx.x;    // 0..17
    int which = blockIdx.y;    // 0=k, 1=q
    int b     = blockIdx.z;
    const float* src = g_qkv + (size_t)b * NR * NNP + (which ? 0 : (size_t)ND * NNP);
    uint32_t* dst = (which ? g_Qfh : g_Kfh) + ((size_t)b * NIT + tile) * 2048;

    __shared__ float st[32][132];
    __shared__ uint32_t sp[2048];
    int t = threadIdx.x;       // 0..127
    int j0 = tile * 128;
#pragma unroll
    for (int d = 0; d < 32; d++)
        st[d][t] = src[(size_t)d * NNP + j0 + t];
    __syncthreads();

    float v[32];
#pragma unroll
    for (int d = 0; d < 32; d++) v[d] = st[d][t];

    if (which == 0) {
        // A-fragment: slot(m,kp) within block of 8 m16-tiles
        int mt = t >> 4;
        int lanebase = (t & 7) * 4;
        int madd = (t >> 3) & 1;
#pragma unroll
        for (int kp = 0; kp < 16; kp++) {
            uint32_t h = packh2(v[2 * kp], v[2 * kp + 1]);
            int idx = ((mt * 2 + (kp >> 3)) * 32 + lanebase + (kp & 3)) * 4 + madd + 2 * ((kp >> 2) & 1);
            sp[idx] = h;
        }
    } else {
        // B-fragment: slot(n,kp) within block of 16 n8-tiles
        int nt = t >> 3;
        int lanebase = (t & 7) * 4;
#pragma unroll
        for (int kp = 0; kp < 16; kp++) {
            uint32_t h = packh2(v[2 * kp], v[2 * kp + 1]);
            int idx = ((nt * 2 + (kp >> 3)) * 32 + lanebase + (kp & 3)) * 2 + ((kp >> 2) & 1);
            sp[idx] = h;
        }
    }
    __syncthreads();
    uint4* d4 = (uint4*)dst;
    const uint4* s4 = (const uint4*)sp;
#pragma unroll
    for (int u = 0; u < 4; u++) d4[t + u * 128] = s4[t + u * 128];
}

// ---------------------------------------------------------------------------
// K2: energy via fp16 mma — E^T[j][i] = k_j . q_i, fp32 output.
// Block: 128 j x 128 i, K=32 (2 k-steps). One 16KB cp.async, 32 mmas/warp.
// ---------------------------------------------------------------------------
__global__ __launch_bounds__(256) void energy_tc_kernel() {
    int it = blockIdx.x;      // i-tile 0..17
    int jt = blockIdx.y;      // j-tile 0..17
    int b  = blockIdx.z;

    __shared__ uint32_t sm[4096];          // A 2048 + B 2048
    uint32_t* sA = sm;
    uint32_t* sB = sm + 2048;
    const uint32_t* srcA = g_Kfh + ((size_t)b * NIT + jt) * 2048;
    const uint32_t* srcB = g_Qfh + ((size_t)b * NIT + it) * 2048;
    int tid = threadIdx.x;
#pragma unroll
    for (int u = 0; u < 2; u++) {
        cp_async16((uint4*)sA + tid + u * 256, (const uint4*)srcA + tid + u * 256);
        cp_async16((uint4*)sB + tid + u * 256, (const uint4*)srcB + tid + u * 256);
    }
    CP_COMMIT();

    const int lane = tid & 31;
    const int wid = tid >> 5;
    const int warp_m = wid & 1;    // 2 x 64 j
    const int warp_n = wid >> 1;   // 4 x 32 i

    float acc[4][4][4];
#pragma unroll
    for (int i = 0; i < 4; i++)
#pragma unroll
        for (int j = 0; j < 4; j++)
#pragma unroll
            for (int r = 0; r < 4; r++) acc[i][j][r] = 0.f;

    CP_WAIT(0);
    __syncthreads();

#pragma unroll
    for (int ks = 0; ks < 2; ks++) {
        uint32_t a[4][4], bfr[4][2];
#pragma unroll
        for (int i = 0; i < 4; i++) {
            int mt = warp_m * 4 + i;
            uint4 tdat = *(const uint4*)(sA + ((mt * 2 + ks) * 32 + lane) * 4);
            a[i][0] = tdat.x; a[i][1] = tdat.y; a[i][2] = tdat.z; a[i][3] = tdat.w;
        }
#pragma unroll
        for (int j = 0; j < 4; j++) {
            int nt = warp_n * 4 + j;
            uint2 tdat = *(const uint2*)(sB + ((nt * 2 + ks) * 32 + lane) * 2);
            bfr[j][0] = tdat.x; bfr[j][1] = tdat.y;
        }
#pragma unroll
        for (int i = 0; i < 4; i++)
#pragma unroll
            for (int j = 0; j < 4; j++)
                mma_f16(acc[i][j], a[i], bfr[j]);
    }

    // epilogue: fp32 float2 stores into E^T[j][i]
    float* Eb = g_energy + (size_t)b * NNP * NNP;
    const int gq = lane >> 2, tq = lane & 3;
    int j0 = jt * 128, i0 = it * 128;
#pragma unroll
    for (int i = 0; i < 4; i++) {
        int r0 = j0 + warp_m * 64 + i * 16 + gq;
#pragma unroll
        for (int j = 0; j < 4; j++) {
            int c = i0 + warp_n * 32 + j * 8 + tq * 2;
            float2 v0; v0.x = acc[i][j][0]; v0.y = acc[i][j][1];
            float2 v1; v1.x = acc[i][j][2]; v1.y = acc[i][j][3];
            *(float2*)(Eb + (size_t)r0 * NNP + c) = v0;
            *(float2*)(Eb + (size_t)(r0 + 8) * NNP + c) = v1;
        }
    }
}

// ---------------------------------------------------------------------------
// K3: per-key-column stats  L[j] = max_i + log(sum_i exp)
// ---------------------------------------------------------------------------
__global__ __launch_bounds__(256) void softmax_stats_kernel() {
    int b = blockIdx.y;
    int j = blockIdx.x;
    const float* row = g_energy + (size_t)b * NNP * NNP + (size_t)j * NNP;
    int tid = threadIdx.x;

    float vals[9];
    float m = -1e30f;
#pragma unroll
    for (int u = 0; u < 9; u++) {
        vals[u] = row[tid + u * 256];
        m = fmaxf(m, vals[u]);
    }
    __shared__ float red[256];
    red[tid] = m; __syncthreads();
    for (int s = 128; s > 0; s >>= 1) {
        if (tid < s) red[tid] = fmaxf(red[tid], red[tid + s]);
        __syncthreads();
    }
    m = red[0]; __syncthreads();
    float sum = 0.f;
#pragma unroll
    for (int u = 0; u < 9; u++) sum += __expf(vals[u] - m);
    red[tid] = sum; __syncthreads();
    for (int s = 128; s > 0; s >>= 1) {
        if (tid < s) red[tid] += red[tid + s];
        __syncthreads();
    }
    if (tid == 0) g_L[b * NNP + j] = m + __logf(red[0]);
}

// ---------------------------------------------------------------------------
// K3b: p_pack_h — P = exp(E^T - L) as fp16 pairs in m16n8k16 B-fragment order.
// ---------------------------------------------------------------------------
__global__ __launch_bounds__(256) void p_pack_h_kernel() {
    int itile = blockIdx.x;         // 0..17
    int kc = blockIdx.y;            // 0..71
    int b  = blockIdx.z;
    const float* E = g_energy + (size_t)b * NNP * NNP + (size_t)(kc * 32) * NNP + itile * 128;
    const float* Lr = g_L + b * NNP + kc * 32;
    __shared__ uint32_t sp[2048];
    int t = threadIdx.x;
    int kp = t & 15;
    int nb = t >> 4;
    int k0 = kp * 2;
    float L0 = Lr[k0], L1 = Lr[k0 + 1];
    const float* r0 = E + (size_t)k0 * NNP + nb * 8;
    const float* r1 = r0 + NNP;
    float e0[8], e1[8];
    *(float4*)&e0[0] = *(const float4*)r0;  *(float4*)&e0[4] = *(const float4*)(r0 + 4);
    *(float4*)&e1[0] = *(const float4*)r1;  *(float4*)&e1[4] = *(const float4*)(r1 + 4);
    int ks = kp >> 3, rg = (kp >> 2) & 1, kl = kp & 3;
    int base = ((nb * 2 + ks) * 32 + kl) * 2 + rg;
#pragma unroll
    for (int u = 0; u < 8; u++)
        sp[base + u * 8] = packh2(__expf(e0[u] - L0), __expf(e1[u] - L1));
    __syncthreads();
    uint4* dst = (uint4*)(g_Ph + (((size_t)b * NIT + itile) * NKC + kc) * 2048);
    const uint4* src = (const uint4*)sp;
    dst[t] = src[t];
    dst[t + 256] = src[t + 256];
}

// ---------------------------------------------------------------------------
// K1b: vf_pack_h — v as fp16 pairs in m16n8k16 A-fragment order.
// ---------------------------------------------------------------------------
__global__ __launch_bounds__(256) void vf_pack_h_kernel() {
    int kc = blockIdx.x;     // 0..71
    int b  = blockIdx.y;
    const float* V = g_qkv + (size_t)b * NR * NNP + (size_t)(2 * ND) * NNP;
    __shared__ uint32_t sa[4096];
    int t = threadIdx.x;     // = channel row m
    const float* row = V + (size_t)t * NNP + kc * 32;
    float v[32];
#pragma unroll
    for (int u = 0; u < 8; u++) *(float4*)&v[u * 4] = *(const float4*)(row + u * 4);
    int mt = t >> 4;
    int lanebase = (t & 7) * 4;
    int madd = (t >> 3) & 1;
#pragma unroll
    for (int kp = 0; kp < 16; kp++) {
        uint32_t h = packh2(v[2 * kp], v[2 * kp + 1]);
        int idx = ((mt * 2 + (kp >> 3)) * 32 + lanebase + (kp & 3)) * 4 + madd + 2 * ((kp >> 2) & 1);
        sa[idx] = h;
    }
    __syncthreads();
    uint4* dst = (uint4*)(g_Vfh + ((size_t)b * NKC + kc) * 4096);
    const uint4* src = (const uint4*)sa;
#pragma unroll
    for (int u = 0; u < 4; u++) dst[t + u * 256] = src[t + u * 256];
}

// ---------------------------------------------------------------------------
// K4: out = gamma * (V @ P) + x  via mma.sync fp16 (m16n8k16), f32 accum.
// CTA: M=256 x N=128; K chunks of 32; 3-stage cp.async ring.
// ---------------------------------------------------------------------------
#define ITERS NKC
#define S_STAGE 6144                    // uints per stage: A 4096 + B 2048
#define S_TOTAL3 (3 * S_STAGE * 4)      // 72 KB

__device__ __forceinline__ void og_prefetch(uint32_t* smem, const uint32_t* Vb, const uint32_t* Pb,
                                            int it, int slot, int tid) {
    uint32_t* sA = smem + slot * S_STAGE;
    uint32_t* sB = sA + 4096;
    const uint4* srcA = (const uint4*)(Vb + (size_t)it * 4096);
    const uint4* srcB = (const uint4*)(Pb + (size_t)it * 2048);
#pragma unroll
    for (int u = 0; u < 4; u++)
        cp_async16((uint4*)sA + tid + u * 256, srcA + tid + u * 256);
#pragma unroll
    for (int u = 0; u < 2; u++)
        cp_async16((uint4*)sB + tid + u * 256, srcB + tid + u * 256);
    CP_COMMIT();
}

__global__ __launch_bounds__(256, 1) void out_gemm_tc_kernel(const float* __restrict__ x,
                                                             const float* __restrict__ gamma,
                                                             float* __restrict__ out) {
    extern __shared__ uint32_t smem[];
    const int tid = threadIdx.x;
    const int lane = tid & 31;
    const int wid = tid >> 5;
    const int warp_m = wid & 3;        // 4 m-tiles of 64 rows
    const int warp_n = wid >> 2;       // 2 n-tiles of 64 cols

    const int itile = blockIdx.x;      // 0..17
    const int b = blockIdx.y;

    const uint32_t* Vb = g_Vfh + (size_t)b * NKC * 4096;
    const uint32_t* Pb = g_Ph + (((size_t)b * NIT + itile) * NKC) * 2048;

    float acc[4][8][4];
#pragma unroll
    for (int i = 0; i < 4; i++)
#pragma unroll
        for (int j = 0; j < 8; j++)
#pragma unroll
            for (int r = 0; r < 4; r++) acc[i][j][r] = 0.f;

    og_prefetch(smem, Vb, Pb, 0, 0, tid);
    og_prefetch(smem, Vb, Pb, 1, 1, tid);

    int slot = 0, nslot = 2;
    for (int it = 0; it < ITERS; it++) {
        if (it < ITERS - 1) { CP_WAIT(1); } else { CP_WAIT(0); }
        __syncthreads();
        if (it + 2 < ITERS) {
            og_prefetch(smem, Vb, Pb, it + 2, nslot, tid);
            if (++nslot == 3) nslot = 0;
        }

        const uint32_t* uA = smem + slot * S_STAGE;
        const uint32_t* uB = uA + 4096;
        if (++slot == 3) slot = 0;
#pragma unroll
        for (int ks = 0; ks < 2; ks++) {
            uint32_t a[4][4];
            uint32_t bfr[8][2];
#pragma unroll
            for (int i = 0; i < 4; i++) {
                int mt = warp_m * 4 + i;
                uint4 tdat = *(const uint4*)(uA + ((mt * 2 + ks) * 32 + lane) * 4);
                a[i][0] = tdat.x; a[i][1] = tdat.y; a[i][2] = tdat.z; a[i][3] = tdat.w;
            }
#pragma unroll
            for (int j = 0; j < 8; j++) {
                int nt = warp_n * 8 + j;
                uint2 tdat = *(const uint2*)(uB + ((nt * 2 + ks) * 32 + lane) * 2);
                bfr[j][0] = tdat.x; bfr[j][1] = tdat.y;
            }
#pragma unroll
            for (int i = 0; i < 4; i++)
#pragma unroll
                for (int j = 0; j < 8; j++)
                    mma_f16(acc[i][j], a[i], bfr[j]);
        }
    }

    // ---- epilogue: gamma*acc + x, float2 stores ----
    const float g = gamma[0];
    const float* xb = x + (size_t)b * NC * NNP;
    float* ob = out + (size_t)b * NC * NNP;
    const int gq = lane >> 2, tq = lane & 3;
#pragma unroll
    for (int i = 0; i < 4; i++) {
        int row0 = warp_m * 64 + i * 16 + gq;
#pragma unroll
        for (int j = 0; j < 8; j++) {
            int n = itile * 128 + warp_n * 64 + j * 8 + tq * 2;
            size_t o0 = (size_t)row0 * NNP + n;
            size_t o1 = o0 + (size_t)8 * NNP;
            float2 x0 = *(const float2*)(xb + o0);
            float2 x1 = *(const float2*)(xb + o1);
            float2 r0, r1;
            r0.x = g * acc[i][j][0] + x0.x;
            r0.y = g * acc[i][j][1] + x0.y;
            r1.x = g * acc[i][j][2] + x1.x;
            r1.y = g * acc[i][j][3] + x1.y;
            *(float2*)(ob + o0) = r0;
            *(float2*)(ob + o1) = r1;
        }
    }
}

// ---------------------------------------------------------------------------
extern "C" void kernel_launch(void* const* d_in, const int* in_sizes, int n_in,
                              void* d_out, int out_size) {
    const float* x     = (const float*)d_in[0];
    const float* Wq    = (const float*)d_in[1];
    const float* bq    = (const float*)d_in[2];
    const float* Wk    = (const float*)d_in[3];
    const float* bk    = (const float*)d_in[4];
    const float* Wv    = (const float*)d_in[5];
    const float* bv    = (const float*)d_in[6];
    const float* gamma = (const float*)d_in[7];
    float* out = (float*)d_out;

    pack_w_kernel<<<(NR * NC + 255) / 256, 256>>>(Wq, bq, Wk, bk, Wv, bv);

    dim3 g1(NNP / 64, NR / 64, NB);
    qkv_gemm_kernel<<<g1, 256>>>(x);

    dim3 gqk(NIT, 2, NB);
    qk_pack_kernel<<<gqk, 128>>>();

    dim3 g2(NIT, NIT, NB);
    energy_tc_kernel<<<g2, 256>>>();

    dim3 g3(NNP, NB);
    softmax_stats_kernel<<<g3, 256>>>();

    dim3 gv(NKC, NB);
    vf_pack_h_kernel<<<gv, 256>>>();

    dim3 gp(NIT, NKC, NB);
    p_pack_h_kernel<<<gp, 256>>>();

    cudaFuncSetAttribute(out_gemm_tc_kernel, cudaFuncAttributeMaxDynamicSharedMemorySize, S_TOTAL3);
    dim3 g4(NIT, NB);
    out_gemm_tc_kernel<<<g4, 256, S_TOTAL3>>>(x, gamma, out);
}

// round 13
// speedup vs baseline: 1.4961x; 1.0622x over previous
#include <cuda_runtime.h>
#include <cuda_fp16.h>
#include <math.h>
#include <cstdint>

#define NB 16
#define NC 256
#define NNP 2304   // N = 48*48 pixels
#define ND 32      // d = C/8
#define NR 320     // packed qkv rows: 32 q + 32 k + 256 v
#define NKC 72     // k-chunks of 32 in NNP
#define NIT 18     // 128-pixel i-tiles in NNP

// ---- scratch (static device globals; no allocation at runtime) ----
__device__ float g_W[NR * NC];
__device__ float g_bias[NR];
__device__ float g_qkv[(size_t)NB * NR * NNP];            // 47 MB
__device__ __half g_energyh[(size_t)NB * NNP * NNP];      // 170 MB, E^T[j][i] fp16
__device__ float g_L[NB * NNP];                           // M[j] + log S[j]
__device__ uint32_t g_Ph[(size_t)NB * NIT * NKC * 2048];  // 170 MB, fp16 fragment-ordered probs
__device__ uint32_t g_Vfh[(size_t)NB * NKC * 4096];       // 19 MB, fp16 fragment-ordered v
__device__ uint32_t g_Kfh[(size_t)NB * NIT * 2048];       // 2.4 MB, fp16 A-fragment k (per j-tile)
__device__ uint32_t g_Qfh[(size_t)NB * NIT * 2048];       // 2.4 MB, fp16 B-fragment q (per i-tile)

__device__ __forceinline__ uint32_t packh2(float lo, float hi) {
    __half2 h = __floats2half2_rn(lo, hi);
    return *reinterpret_cast<uint32_t*>(&h);
}
__device__ __forceinline__ void mma_f16(float* c, const uint32_t* a, const uint32_t* b) {
    asm volatile(
        "mma.sync.aligned.m16n8k16.row.col.f32.f16.f16.f32 "
        "{%0,%1,%2,%3}, {%4,%5,%6,%7}, {%8,%9}, {%0,%1,%2,%3};"
        : "+f"(c[0]), "+f"(c[1]), "+f"(c[2]), "+f"(c[3])
        : "r"(a[0]), "r"(a[1]), "r"(a[2]), "r"(a[3]), "r"(b[0]), "r"(b[1]));
}
__device__ __forceinline__ void cp_async16(void* smem_dst, const void* gmem_src) {
    uint32_t sa = (uint32_t)__cvta_generic_to_shared(smem_dst);
    asm volatile("cp.async.cg.shared.global [%0], [%1], 16;" :: "r"(sa), "l"(gmem_src));
}
#define CP_COMMIT() asm volatile("cp.async.commit_group;" ::: "memory")
#define CP_WAIT(n)  asm volatile("cp.async.wait_group %0;" :: "n"(n) : "memory")

// ---------------------------------------------------------------------------
// K0: pack weights + biases
// ---------------------------------------------------------------------------
__global__ void pack_w_kernel(const float* __restrict__ Wq, const float* __restrict__ bq,
                              const float* __restrict__ Wk, const float* __restrict__ bk,
                              const float* __restrict__ Wv, const float* __restrict__ bv) {
    int idx = blockIdx.x * blockDim.x + threadIdx.x;
    if (idx < NR * NC) {
        int r = idx / NC, c = idx - r * NC;
        float v;
        if (r < ND)          v = Wq[r * NC + c];
        else if (r < 2 * ND) v = Wk[(r - ND) * NC + c];
        else                 v = Wv[(r - 2 * ND) * NC + c];
        g_W[idx] = v;
    }
    if (idx < NR) {
        float v;
        if (idx < ND)          v = bq[idx];
        else if (idx < 2 * ND) v = bk[idx - ND];
        else                   v = bv[idx - 2 * ND];
        g_bias[idx] = v;
    }
}

// ---------------------------------------------------------------------------
// K1: qkv projection GEMM (fp32 SIMT)
// ---------------------------------------------------------------------------
__global__ __launch_bounds__(256) void qkv_gemm_kernel(const float* __restrict__ x) {
    int b = blockIdx.z;
    int m0 = blockIdx.y * 64;
    int n0 = blockIdx.x * 64;
    const float* A  = g_W;
    const float* Bm = x + (size_t)b * NC * NNP;
    float* Cm = g_qkv + (size_t)b * NR * NNP;

    __shared__ float As[16][64];
    __shared__ float Bs[16][64];
    int tid = threadIdx.x;
    int tx = tid & 15, ty = tid >> 4;
    float acc[4][4] = {};

    for (int k0 = 0; k0 < NC; k0 += 16) {
        int ar = tid >> 2, ac = (tid & 3) * 4;
        float4 av = *(const float4*)(A + (size_t)(m0 + ar) * NC + k0 + ac);
        As[ac + 0][ar] = av.x; As[ac + 1][ar] = av.y;
        As[ac + 2][ar] = av.z; As[ac + 3][ar] = av.w;
        int br = tid >> 4, bc = (tid & 15) * 4;
        *(float4*)&Bs[br][bc] = *(const float4*)(Bm + (size_t)(k0 + br) * NNP + n0 + bc);
        __syncthreads();
#pragma unroll
        for (int kk = 0; kk < 16; kk++) {
            float a[4], bb[4];
            *(float4*)a  = *(const float4*)&As[kk][ty * 4];
            *(float4*)bb = *(const float4*)&Bs[kk][tx * 4];
#pragma unroll
            for (int i = 0; i < 4; i++)
#pragma unroll
                for (int j = 0; j < 4; j++)
                    acc[i][j] += a[i] * bb[j];
        }
        __syncthreads();
    }
#pragma unroll
    for (int i = 0; i < 4; i++) {
        int m = m0 + ty * 4 + i;
        float bias = g_bias[m];
        float4 o;
        o.x = acc[i][0] + bias; o.y = acc[i][1] + bias;
        o.z = acc[i][2] + bias; o.w = acc[i][3] + bias;
        *(float4*)(Cm + (size_t)m * NNP + n0 + tx * 4) = o;
    }
}

// ---------------------------------------------------------------------------
// K1c: qk_pack — q and k as fp16 pairs in mma fragment order, per 128-tile.
// ---------------------------------------------------------------------------
__global__ __launch_bounds__(128) void qk_pack_kernel() {
    int tile  = blockIdx.x;    // 0..17
    int which = blockIdx.y;    // 0=k, 1=q
    int b     = blockIdx.z;
    const float* src = g_qkv + (size_t)b * NR * NNP + (which ? 0 : (size_t)ND * NNP);
    uint32_t* dst = (which ? g_Qfh : g_Kfh) + ((size_t)b * NIT + tile) * 2048;

    __shared__ float st[32][132];
    __shared__ uint32_t sp[2048];
    int t = threadIdx.x;       // 0..127
    int j0 = tile * 128;
#pragma unroll
    for (int d = 0; d < 32; d++)
        st[d][t] = src[(size_t)d * NNP + j0 + t];
    __syncthreads();

    float v[32];
#pragma unroll
    for (int d = 0; d < 32; d++) v[d] = st[d][t];

    if (which == 0) {
        int mt = t >> 4;
        int lanebase = (t & 7) * 4;
        int madd = (t >> 3) & 1;
#pragma unroll
        for (int kp = 0; kp < 16; kp++) {
            uint32_t h = packh2(v[2 * kp], v[2 * kp + 1]);
            int idx = ((mt * 2 + (kp >> 3)) * 32 + lanebase + (kp & 3)) * 4 + madd + 2 * ((kp >> 2) & 1);
            sp[idx] = h;
        }
    } else {
        int nt = t >> 3;
        int lanebase = (t & 7) * 4;
#pragma unroll
        for (int kp = 0; kp < 16; kp++) {
            uint32_t h = packh2(v[2 * kp], v[2 * kp + 1]);
            int idx = ((nt * 2 + (kp >> 3)) * 32 + lanebase + (kp & 3)) * 2 + ((kp >> 2) & 1);
            sp[idx] = h;
        }
    }
    __syncthreads();
    uint4* d4 = (uint4*)dst;
    const uint4* s4 = (const uint4*)sp;
#pragma unroll
    for (int u = 0; u < 4; u++) d4[t + u * 128] = s4[t + u * 128];
}

// ---------------------------------------------------------------------------
// K2: energy via fp16 mma — E^T[j][i] = k_j . q_i, fp16 output (half2 stores).
// ---------------------------------------------------------------------------
__global__ __launch_bounds__(256) void energy_tc_kernel() {
    int it = blockIdx.x;      // i-tile 0..17
    int jt = blockIdx.y;      // j-tile 0..17
    int b  = blockIdx.z;

    __shared__ uint32_t sm[4096];          // A 2048 + B 2048
    uint32_t* sA = sm;
    uint32_t* sB = sm + 2048;
    const uint32_t* srcA = g_Kfh + ((size_t)b * NIT + jt) * 2048;
    const uint32_t* srcB = g_Qfh + ((size_t)b * NIT + it) * 2048;
    int tid = threadIdx.x;
#pragma unroll
    for (int u = 0; u < 2; u++) {
        cp_async16((uint4*)sA + tid + u * 256, (const uint4*)srcA + tid + u * 256);
        cp_async16((uint4*)sB + tid + u * 256, (const uint4*)srcB + tid + u * 256);
    }
    CP_COMMIT();

    const int lane = tid & 31;
    const int wid = tid >> 5;
    const int warp_m = wid & 1;    // 2 x 64 j
    const int warp_n = wid >> 1;   // 4 x 32 i

    float acc[4][4][4];
#pragma unroll
    for (int i = 0; i < 4; i++)
#pragma unroll
        for (int j = 0; j < 4; j++)
#pragma unroll
            for (int r = 0; r < 4; r++) acc[i][j][r] = 0.f;

    CP_WAIT(0);
    __syncthreads();

#pragma unroll
    for (int ks = 0; ks < 2; ks++) {
        uint32_t a[4][4], bfr[4][2];
#pragma unroll
        for (int i = 0; i < 4; i++) {
            int mt = warp_m * 4 + i;
            uint4 tdat = *(const uint4*)(sA + ((mt * 2 + ks) * 32 + lane) * 4);
            a[i][0] = tdat.x; a[i][1] = tdat.y; a[i][2] = tdat.z; a[i][3] = tdat.w;
        }
#pragma unroll
        for (int j = 0; j < 4; j++) {
            int nt = warp_n * 4 + j;
            uint2 tdat = *(const uint2*)(sB + ((nt * 2 + ks) * 32 + lane) * 2);
            bfr[j][0] = tdat.x; bfr[j][1] = tdat.y;
        }
#pragma unroll
        for (int i = 0; i < 4; i++)
#pragma unroll
            for (int j = 0; j < 4; j++)
                mma_f16(acc[i][j], a[i], bfr[j]);
    }

    // epilogue: half2 stores into E^T[j][i]
    __half* Eb = g_energyh + (size_t)b * NNP * NNP;
    const int gq = lane >> 2, tq = lane & 3;
    int j0 = jt * 128, i0 = it * 128;
#pragma unroll
    for (int i = 0; i < 4; i++) {
        int r0 = j0 + warp_m * 64 + i * 16 + gq;
#pragma unroll
        for (int j = 0; j < 4; j++) {
            int c = i0 + warp_n * 32 + j * 8 + tq * 2;
            *(uint32_t*)(Eb + (size_t)r0 * NNP + c) = packh2(acc[i][j][0], acc[i][j][1]);
            *(uint32_t*)(Eb + (size_t)(r0 + 8) * NNP + c) = packh2(acc[i][j][2], acc[i][j][3]);
        }
    }
}

// ---------------------------------------------------------------------------
// K3: per-key-column stats  L[j] = max_i + log(sum_i exp)   (fp16 E reads)
// ---------------------------------------------------------------------------
__global__ __launch_bounds__(256) void softmax_stats_kernel() {
    int b = blockIdx.y;
    int j = blockIdx.x;
    const __half* row = g_energyh + (size_t)b * NNP * NNP + (size_t)j * NNP;
    int tid = threadIdx.x;

    float vals[9];
    float m = -1e30f;
#pragma unroll
    for (int u = 0; u < 9; u++) {
        vals[u] = __half2float(row[tid + u * 256]);
        m = fmaxf(m, vals[u]);
    }
    __shared__ float red[256];
    red[tid] = m; __syncthreads();
    for (int s = 128; s > 0; s >>= 1) {
        if (tid < s) red[tid] = fmaxf(red[tid], red[tid + s]);
        __syncthreads();
    }
    m = red[0]; __syncthreads();
    float sum = 0.f;
#pragma unroll
    for (int u = 0; u < 9; u++) sum += __expf(vals[u] - m);
    red[tid] = sum; __syncthreads();
    for (int s = 128; s > 0; s >>= 1) {
        if (tid < s) red[tid] += red[tid + s];
        __syncthreads();
    }
    if (tid == 0) g_L[b * NNP + j] = m + __logf(red[0]);
}

// ---------------------------------------------------------------------------
// K3b: p_pack_h — P = exp(E^T - L) fp16 pairs in m16n8k16 B-fragment order.
// fp16 E reads: one uint4 = 8 halfs per row per thread.
// ---------------------------------------------------------------------------
__global__ __launch_bounds__(256) void p_pack_h_kernel() {
    int itile = blockIdx.x;         // 0..17
    int kc = blockIdx.y;            // 0..71
    int b  = blockIdx.z;
    const __half* E = g_energyh + (size_t)b * NNP * NNP + (size_t)(kc * 32) * NNP + itile * 128;
    const float* Lr = g_L + b * NNP + kc * 32;
    __shared__ uint32_t sp[2048];
    int t = threadIdx.x;
    int kp = t & 15;
    int nb = t >> 4;
    int k0 = kp * 2;
    float L0 = Lr[k0], L1 = Lr[k0 + 1];
    uint4 w0 = *(const uint4*)(E + (size_t)k0 * NNP + nb * 8);
    uint4 w1 = *(const uint4*)(E + (size_t)(k0 + 1) * NNP + nb * 8);
    const __half2* h0 = (const __half2*)&w0;
    const __half2* h1 = (const __half2*)&w1;
    float e0[8], e1[8];
#pragma unroll
    for (int u = 0; u < 4; u++) {
        float2 f0 = __half22float2(h0[u]);
        float2 f1 = __half22float2(h1[u]);
        e0[2 * u] = f0.x; e0[2 * u + 1] = f0.y;
        e1[2 * u] = f1.x; e1[2 * u + 1] = f1.y;
    }
    int ks = kp >> 3, rg = (kp >> 2) & 1, kl = kp & 3;
    int base = ((nb * 2 + ks) * 32 + kl) * 2 + rg;
#pragma unroll
    for (int u = 0; u < 8; u++)
        sp[base + u * 8] = packh2(__expf(e0[u] - L0), __expf(e1[u] - L1));
    __syncthreads();
    uint4* dst = (uint4*)(g_Ph + (((size_t)b * NIT + itile) * NKC + kc) * 2048);
    const uint4* src = (const uint4*)sp;
    dst[t] = src[t];
    dst[t + 256] = src[t + 256];
}

// ---------------------------------------------------------------------------
// K1b: vf_pack_h — v as fp16 pairs in m16n8k16 A-fragment order.
// ---------------------------------------------------------------------------
__global__ __launch_bounds__(256) void vf_pack_h_kernel() {
    int kc = blockIdx.x;     // 0..71
    int b  = blockIdx.y;
    const float* V = g_qkv + (size_t)b * NR * NNP + (size_t)(2 * ND) * NNP;
    __shared__ uint32_t sa[4096];
    int t = threadIdx.x;     // = channel row m
    const float* row = V + (size_t)t * NNP + kc * 32;
    float v[32];
#pragma unroll
    for (int u = 0; u < 8; u++) *(float4*)&v[u * 4] = *(const float4*)(row + u * 4);
    int mt = t >> 4;
    int lanebase = (t & 7) * 4;
    int madd = (t >> 3) & 1;
#pragma unroll
    for (int kp = 0; kp < 16; kp++) {
        uint32_t h = packh2(v[2 * kp], v[2 * kp + 1]);
        int idx = ((mt * 2 + (kp >> 3)) * 32 + lanebase + (kp & 3)) * 4 + madd + 2 * ((kp >> 2) & 1);
        sa[idx] = h;
    }
    __syncthreads();
    uint4* dst = (uint4*)(g_Vfh + ((size_t)b * NKC + kc) * 4096);
    const uint4* src = (const uint4*)sa;
#pragma unroll
    for (int u = 0; u < 4; u++) dst[t + u * 256] = src[t + u * 256];
}

// ---------------------------------------------------------------------------
// K4: out = gamma * (V @ P) + x  via mma.sync fp16 (m16n8k16), f32 accum.
// CTA: M=256 x N=128; K chunks of 32; 3-stage cp.async ring.
// ---------------------------------------------------------------------------
#define ITERS NKC
#define S_STAGE 6144                    // uints per stage: A 4096 + B 2048
#define S_TOTAL3 (3 * S_STAGE * 4)      // 72 KB

__device__ __forceinline__ void og_prefetch(uint32_t* smem, const uint32_t* Vb, const uint32_t* Pb,
                                            int it, int slot, int tid) {
    uint32_t* sA = smem + slot * S_STAGE;
    uint32_t* sB = sA + 4096;
    const uint4* srcA = (const uint4*)(Vb + (size_t)it * 4096);
    const uint4* srcB = (const uint4*)(Pb + (size_t)it * 2048);
#pragma unroll
    for (int u = 0; u < 4; u++)
        cp_async16((uint4*)sA + tid + u * 256, srcA + tid + u * 256);
#pragma unroll
    for (int u = 0; u < 2; u++)
        cp_async16((uint4*)sB + tid + u * 256, srcB + tid + u * 256);
    CP_COMMIT();
}

__global__ __launch_bounds__(256, 1) void out_gemm_tc_kernel(const float* __restrict__ x,
                                                             const float* __restrict__ gamma,
                                                             float* __restrict__ out) {
    extern __shared__ uint32_t smem[];
    const int tid = threadIdx.x;
    const int lane = tid & 31;
    const int wid = tid >> 5;
    const int warp_m = wid & 3;        // 4 m-tiles of 64 rows
    const int warp_n = wid >> 2;       // 2 n-tiles of 64 cols

    const int itile = blockIdx.x;      // 0..17
    const int b = blockIdx.y;

    const uint32_t* Vb = g_Vfh + (size_t)b * NKC * 4096;
    const uint32_t* Pb = g_Ph + (((size_t)b * NIT + itile) * NKC) * 2048;

    float acc[4][8][4];
#pragma unroll
    for (int i = 0; i < 4; i++)
#pragma unroll
        for (int j = 0; j < 8; j++)
#pragma unroll
            for (int r = 0; r < 4; r++) acc[i][j][r] = 0.f;

    og_prefetch(smem, Vb, Pb, 0, 0, tid);
    og_prefetch(smem, Vb, Pb, 1, 1, tid);

    int slot = 0, nslot = 2;
    for (int it = 0; it < ITERS; it++) {
        if (it < ITERS - 1) { CP_WAIT(1); } else { CP_WAIT(0); }
        __syncthreads();
        if (it + 2 < ITERS) {
            og_prefetch(smem, Vb, Pb, it + 2, nslot, tid);
            if (++nslot == 3) nslot = 0;
        }

        const uint32_t* uA = smem + slot * S_STAGE;
        const uint32_t* uB = uA + 4096;
        if (++slot == 3) slot = 0;
#pragma unroll
        for (int ks = 0; ks < 2; ks++) {
            uint32_t a[4][4];
            uint32_t bfr[8][2];
#pragma unroll
            for (int i = 0; i < 4; i++) {
                int mt = warp_m * 4 + i;
                uint4 tdat = *(const uint4*)(uA + ((mt * 2 + ks) * 32 + lane) * 4);
                a[i][0] = tdat.x; a[i][1] = tdat.y; a[i][2] = tdat.z; a[i][3] = tdat.w;
            }
#pragma unroll
            for (int j = 0; j < 8; j++) {
                int nt = warp_n * 8 + j;
                uint2 tdat = *(const uint2*)(uB + ((nt * 2 + ks) * 32 + lane) * 2);
                bfr[j][0] = tdat.x; bfr[j][1] = tdat.y;
            }
#pragma unroll
            for (int i = 0; i < 4; i++)
#pragma unroll
                for (int j = 0; j < 8; j++)
                    mma_f16(acc[i][j], a[i], bfr[j]);
        }
    }

    // ---- epilogue: gamma*acc + x, float2 stores ----
    const float g = gamma[0];
    const float* xb = x + (size_t)b * NC * NNP;
    float* ob = out + (size_t)b * NC * NNP;
    const int gq = lane >> 2, tq = lane & 3;
#pragma unroll
    for (int i = 0; i < 4; i++) {
        int row0 = warp_m * 64 + i * 16 + gq;
#pragma unroll
        for (int j = 0; j < 8; j++) {
            int n = itile * 128 + warp_n * 64 + j * 8 + tq * 2;
            size_t o0 = (size_t)row0 * NNP + n;
            size_t o1 = o0 + (size_t)8 * NNP;
            float2 x0 = *(const float2*)(xb + o0);
            float2 x1 = *(const float2*)(xb + o1);
            float2 r0, r1;
            r0.x = g * acc[i][j][0] + x0.x;
            r0.y = g * acc[i][j][1] + x0.y;
            r1.x = g * acc[i][j][2] + x1.x;
            r1.y = g * acc[i][j][3] + x1.y;
            *(float2*)(ob + o0) = r0;
            *(float2*)(ob + o1) = r1;
        }
    }
}

// ---------------------------------------------------------------------------
extern "C" void kernel_launch(void* const* d_in, const int* in_sizes, int n_in,
                              void* d_out, int out_size) {
    const float* x     = (const float*)d_in[0];
    const float* Wq    = (const float*)d_in[1];
    const float* bq    = (const float*)d_in[2];
    const float* Wk    = (const float*)d_in[3];
    const float* bk    = (const float*)d_in[4];
    const float* Wv    = (const float*)d_in[5];
    const float* bv    = (const float*)d_in[6];
    const float* gamma = (const float*)d_in[7];
    float* out = (float*)d_out;

    pack_w_kernel<<<(NR * NC + 255) / 256, 256>>>(Wq, bq, Wk, bk, Wv, bv);

    dim3 g1(NNP / 64, NR / 64, NB);
    qkv_gemm_kernel<<<g1, 256>>>(x);

    dim3 gqk(NIT, 2, NB);
    qk_pack_kernel<<<gqk, 128>>>();

    dim3 g2(NIT, NIT, NB);
    energy_tc_kernel<<<g2, 256>>>();

    dim3 g3(NNP, NB);
    softmax_stats_kernel<<<g3, 256>>>();

    dim3 gv(NKC, NB);
    vf_pack_h_kernel<<<gv, 256>>>();

    dim3 gp(NIT, NKC, NB);
    p_pack_h_kernel<<<gp, 256>>>();

    cudaFuncSetAttribute(out_gemm_tc_kernel, cudaFuncAttributeMaxDynamicSharedMemorySize, S_TOTAL3);
    dim3 g4(NIT, NB);
    out_gemm_tc_kernel<<<g4, 256, S_TOTAL3>>>(x, gamma, out);
}

// round 14
// speedup vs baseline: 1.6282x; 1.0883x over previous
#include <cuda_runtime.h>
#include <cuda_fp16.h>
#include <math.h>
#include <cstdint>

#define NB 16
#define NC 256
#define NNP 2304   // N = 48*48 pixels
#define ND 32      // d = C/8
#define NR 320     // packed qkv rows: 32 q + 32 k + 256 v
#define NKC 72     // k-chunks of 32 in NNP
#define NIT 18     // 128-pixel i-tiles in NNP

// ---- scratch (static device globals; no allocation at runtime) ----
__device__ float g_W[NR * NC];
__device__ float g_bias[NR];
__device__ float g_qkv[(size_t)NB * NR * NNP];            // 47 MB
__device__ __half g_energyh[(size_t)NB * NNP * NNP];      // 170 MB, E^T[j][i] fp16
__device__ float g_Spart[(size_t)NB * NNP * NIT];         // 2.7 MB, per-itile partial rowsums
__device__ float g_invS[NB * NNP];                        // 1 / sum_i exp(e)
__device__ uint32_t g_Ph[(size_t)NB * NIT * NKC * 2048];  // 170 MB, fp16 fragment-ordered probs
__device__ uint32_t g_Vfh[(size_t)NB * NKC * 4096];       // 19 MB, fp16 fragment-ordered v
__device__ uint32_t g_Kfh[(size_t)NB * NIT * 2048];       // 2.4 MB, fp16 A-fragment k (per j-tile)
__device__ uint32_t g_Qfh[(size_t)NB * NIT * 2048];       // 2.4 MB, fp16 B-fragment q (per i-tile)

__device__ __forceinline__ uint32_t packh2(float lo, float hi) {
    __half2 h = __floats2half2_rn(lo, hi);
    return *reinterpret_cast<uint32_t*>(&h);
}
__device__ __forceinline__ void mma_f16(float* c, const uint32_t* a, const uint32_t* b) {
    asm volatile(
        "mma.sync.aligned.m16n8k16.row.col.f32.f16.f16.f32 "
        "{%0,%1,%2,%3}, {%4,%5,%6,%7}, {%8,%9}, {%0,%1,%2,%3};"
        : "+f"(c[0]), "+f"(c[1]), "+f"(c[2]), "+f"(c[3])
        : "r"(a[0]), "r"(a[1]), "r"(a[2]), "r"(a[3]), "r"(b[0]), "r"(b[1]));
}
__device__ __forceinline__ void cp_async16(void* smem_dst, const void* gmem_src) {
    uint32_t sa = (uint32_t)__cvta_generic_to_shared(smem_dst);
    asm volatile("cp.async.cg.shared.global [%0], [%1], 16;" :: "r"(sa), "l"(gmem_src));
}
#define CP_COMMIT() asm volatile("cp.async.commit_group;" ::: "memory")
#define CP_WAIT(n)  asm volatile("cp.async.wait_group %0;" :: "n"(n) : "memory")

// ---------------------------------------------------------------------------
// K0: pack weights + biases
// ---------------------------------------------------------------------------
__global__ void pack_w_kernel(const float* __restrict__ Wq, const float* __restrict__ bq,
                              const float* __restrict__ Wk, const float* __restrict__ bk,
                              const float* __restrict__ Wv, const float* __restrict__ bv) {
    int idx = blockIdx.x * blockDim.x + threadIdx.x;
    if (idx < NR * NC) {
        int r = idx / NC, c = idx - r * NC;
        float v;
        if (r < ND)          v = Wq[r * NC + c];
        else if (r < 2 * ND) v = Wk[(r - ND) * NC + c];
        else                 v = Wv[(r - 2 * ND) * NC + c];
        g_W[idx] = v;
    }
    if (idx < NR) {
        float v;
        if (idx < ND)          v = bq[idx];
        else if (idx < 2 * ND) v = bk[idx - ND];
        else                   v = bv[idx - 2 * ND];
        g_bias[idx] = v;
    }
}

// ---------------------------------------------------------------------------
// K1: qkv projection GEMM (fp32 SIMT)
// ---------------------------------------------------------------------------
__global__ __launch_bounds__(256) void qkv_gemm_kernel(const float* __restrict__ x) {
    int b = blockIdx.z;
    int m0 = blockIdx.y * 64;
    int n0 = blockIdx.x * 64;
    const float* A  = g_W;
    const float* Bm = x + (size_t)b * NC * NNP;
    float* Cm = g_qkv + (size_t)b * NR * NNP;

    __shared__ float As[16][64];
    __shared__ float Bs[16][64];
    int tid = threadIdx.x;
    int tx = tid & 15, ty = tid >> 4;
    float acc[4][4] = {};

    for (int k0 = 0; k0 < NC; k0 += 16) {
        int ar = tid >> 2, ac = (tid & 3) * 4;
        float4 av = *(const float4*)(A + (size_t)(m0 + ar) * NC + k0 + ac);
        As[ac + 0][ar] = av.x; As[ac + 1][ar] = av.y;
        As[ac + 2][ar] = av.z; As[ac + 3][ar] = av.w;
        int br = tid >> 4, bc = (tid & 15) * 4;
        *(float4*)&Bs[br][bc] = *(const float4*)(Bm + (size_t)(k0 + br) * NNP + n0 + bc);
        __syncthreads();
#pragma unroll
        for (int kk = 0; kk < 16; kk++) {
            float a[4], bb[4];
            *(float4*)a  = *(const float4*)&As[kk][ty * 4];
            *(float4*)bb = *(const float4*)&Bs[kk][tx * 4];
#pragma unroll
            for (int i = 0; i < 4; i++)
#pragma unroll
                for (int j = 0; j < 4; j++)
                    acc[i][j] += a[i] * bb[j];
        }
        __syncthreads();
    }
#pragma unroll
    for (int i = 0; i < 4; i++) {
        int m = m0 + ty * 4 + i;
        float bias = g_bias[m];
        float4 o;
        o.x = acc[i][0] + bias; o.y = acc[i][1] + bias;
        o.z = acc[i][2] + bias; o.w = acc[i][3] + bias;
        *(float4*)(Cm + (size_t)m * NNP + n0 + tx * 4) = o;
    }
}

// ---------------------------------------------------------------------------
// K1c: qk_pack — q and k as fp16 pairs in mma fragment order, per 128-tile.
// ---------------------------------------------------------------------------
__global__ __launch_bounds__(128) void qk_pack_kernel() {
    int tile  = blockIdx.x;    // 0..17
    int which = blockIdx.y;    // 0=k, 1=q
    int b     = blockIdx.z;
    const float* src = g_qkv + (size_t)b * NR * NNP + (which ? 0 : (size_t)ND * NNP);
    uint32_t* dst = (which ? g_Qfh : g_Kfh) + ((size_t)b * NIT + tile) * 2048;

    __shared__ float st[32][132];
    __shared__ uint32_t sp[2048];
    int t = threadIdx.x;       // 0..127
    int j0 = tile * 128;
#pragma unroll
    for (int d = 0; d < 32; d++)
        st[d][t] = src[(size_t)d * NNP + j0 + t];
    __syncthreads();

    float v[32];
#pragma unroll
    for (int d = 0; d < 32; d++) v[d] = st[d][t];

    if (which == 0) {
        int mt = t >> 4;
        int lanebase = (t & 7) * 4;
        int madd = (t >> 3) & 1;
#pragma unroll
        for (int kp = 0; kp < 16; kp++) {
            uint32_t h = packh2(v[2 * kp], v[2 * kp + 1]);
            int idx = ((mt * 2 + (kp >> 3)) * 32 + lanebase + (kp & 3)) * 4 + madd + 2 * ((kp >> 2) & 1);
            sp[idx] = h;
        }
    } else {
        int nt = t >> 3;
        int lanebase = (t & 7) * 4;
#pragma unroll
        for (int kp = 0; kp < 16; kp++) {
            uint32_t h = packh2(v[2 * kp], v[2 * kp + 1]);
            int idx = ((nt * 2 + (kp >> 3)) * 32 + lanebase + (kp & 3)) * 2 + ((kp >> 2) & 1);
            sp[idx] = h;
        }
    }
    __syncthreads();
    uint4* d4 = (uint4*)dst;
    const uint4* s4 = (const uint4*)sp;
#pragma unroll
    for (int u = 0; u < 4; u++) d4[t + u * 128] = s4[t + u * 128];
}

// ---------------------------------------------------------------------------
// K2: energy via fp16 mma — E^T[j][i] = k_j . q_i, fp16 store, PLUS per-row
// partial sums of exp(e) (unnormalized softmax; e bounded ~|20| so exp fits
// fp32 easily). Deterministic: block writes its own g_Spart[...][it] slot.
// ---------------------------------------------------------------------------
__global__ __launch_bounds__(256) void energy_tc_kernel() {
    int it = blockIdx.x;      // i-tile 0..17
    int jt = blockIdx.y;      // j-tile 0..17
    int b  = blockIdx.z;

    __shared__ uint32_t sm[4096];          // A 2048 + B 2048
    __shared__ float spart[4][128];
    uint32_t* sA = sm;
    uint32_t* sB = sm + 2048;
    const uint32_t* srcA = g_Kfh + ((size_t)b * NIT + jt) * 2048;
    const uint32_t* srcB = g_Qfh + ((size_t)b * NIT + it) * 2048;
    int tid = threadIdx.x;
#pragma unroll
    for (int u = 0; u < 2; u++) {
        cp_async16((uint4*)sA + tid + u * 256, (const uint4*)srcA + tid + u * 256);
        cp_async16((uint4*)sB + tid + u * 256, (const uint4*)srcB + tid + u * 256);
    }
    CP_COMMIT();

    const int lane = tid & 31;
    const int wid = tid >> 5;
    const int warp_m = wid & 1;    // 2 x 64 j
    const int warp_n = wid >> 1;   // 4 x 32 i
    const int gq = lane >> 2, tq = lane & 3;

    float acc[4][4][4];
#pragma unroll
    for (int i = 0; i < 4; i++)
#pragma unroll
        for (int j = 0; j < 4; j++)
#pragma unroll
            for (int r = 0; r < 4; r++) acc[i][j][r] = 0.f;

    CP_WAIT(0);
    __syncthreads();

#pragma unroll
    for (int ks = 0; ks < 2; ks++) {
        uint32_t a[4][4], bfr[4][2];
#pragma unroll
        for (int i = 0; i < 4; i++) {
            int mt = warp_m * 4 + i;
            uint4 tdat = *(const uint4*)(sA + ((mt * 2 + ks) * 32 + lane) * 4);
            a[i][0] = tdat.x; a[i][1] = tdat.y; a[i][2] = tdat.z; a[i][3] = tdat.w;
        }
#pragma unroll
        for (int j = 0; j < 4; j++) {
            int nt = warp_n * 4 + j;
            uint2 tdat = *(const uint2*)(sB + ((nt * 2 + ks) * 32 + lane) * 2);
            bfr[j][0] = tdat.x; bfr[j][1] = tdat.y;
        }
#pragma unroll
        for (int i = 0; i < 4; i++)
#pragma unroll
            for (int j = 0; j < 4; j++)
                mma_f16(acc[i][j], a[i], bfr[j]);
    }

    // epilogue 1: half2 stores into E^T[j][i]
    __half* Eb = g_energyh + (size_t)b * NNP * NNP;
    int j0 = jt * 128, i0 = it * 128;
#pragma unroll
    for (int i = 0; i < 4; i++) {
        int r0 = j0 + warp_m * 64 + i * 16 + gq;
#pragma unroll
        for (int j = 0; j < 4; j++) {
            int c = i0 + warp_n * 32 + j * 8 + tq * 2;
            *(uint32_t*)(Eb + (size_t)r0 * NNP + c) = packh2(acc[i][j][0], acc[i][j][1]);
            *(uint32_t*)(Eb + (size_t)(r0 + 8) * NNP + c) = packh2(acc[i][j][2], acc[i][j][3]);
        }
    }

    // epilogue 2: per-row (j) partial sums of exp(e) over this block's 32 i's
#pragma unroll
    for (int i = 0; i < 4; i++) {
#pragma unroll
        for (int half = 0; half < 2; half++) {
            float rs = 0.f;
#pragma unroll
            for (int j = 0; j < 4; j++)
                rs += __expf(acc[i][j][half * 2]) + __expf(acc[i][j][half * 2 + 1]);
            rs += __shfl_xor_sync(0xFFFFFFFFu, rs, 1);
            rs += __shfl_xor_sync(0xFFFFFFFFu, rs, 2);
            if (tq == 0)
                spart[warp_n][warp_m * 64 + i * 16 + gq + half * 8] = rs;
        }
    }
    __syncthreads();
    if (tid < 128) {
        float s = spart[0][tid] + spart[1][tid] + spart[2][tid] + spart[3][tid];
        g_Spart[((size_t)b * NNP + jt * 128 + tid) * NIT + it] = s;
    }
}

// ---------------------------------------------------------------------------
// K2b: reduce partials -> invS = 1 / sum_i exp(e)
// ---------------------------------------------------------------------------
__global__ __launch_bounds__(256) void reduce_S_kernel() {
    int idx = blockIdx.x * blockDim.x + threadIdx.x;
    if (idx < NB * NNP) {
        const float* p = g_Spart + (size_t)idx * NIT;
        float s = 0.f;
#pragma unroll
        for (int u = 0; u < NIT; u++) s += p[u];
        g_invS[idx] = 1.0f / s;
    }
}

// ---------------------------------------------------------------------------
// K3b: p_pack_h — P = exp(E^T) * invS, fp16 pairs in m16n8k16 B-frag order.
// ---------------------------------------------------------------------------
__global__ __launch_bounds__(256) void p_pack_h_kernel() {
    int itile = blockIdx.x;         // 0..17
    int kc = blockIdx.y;            // 0..71
    int b  = blockIdx.z;
    const __half* E = g_energyh + (size_t)b * NNP * NNP + (size_t)(kc * 32) * NNP + itile * 128;
    const float* Sr = g_invS + b * NNP + kc * 32;
    __shared__ uint32_t sp[2048];
    int t = threadIdx.x;
    int kp = t & 15;
    int nb = t >> 4;
    int k0 = kp * 2;
    float iS0 = Sr[k0], iS1 = Sr[k0 + 1];
    uint4 w0 = *(const uint4*)(E + (size_t)k0 * NNP + nb * 8);
    uint4 w1 = *(const uint4*)(E + (size_t)(k0 + 1) * NNP + nb * 8);
    const __half2* h0 = (const __half2*)&w0;
    const __half2* h1 = (const __half2*)&w1;
    float e0[8], e1[8];
#pragma unroll
    for (int u = 0; u < 4; u++) {
        float2 f0 = __half22float2(h0[u]);
        float2 f1 = __half22float2(h1[u]);
        e0[2 * u] = f0.x; e0[2 * u + 1] = f0.y;
        e1[2 * u] = f1.x; e1[2 * u + 1] = f1.y;
    }
    int ks = kp >> 3, rg = (kp >> 2) & 1, kl = kp & 3;
    int base = ((nb * 2 + ks) * 32 + kl) * 2 + rg;
#pragma unroll
    for (int u = 0; u < 8; u++)
        sp[base + u * 8] = packh2(__expf(e0[u]) * iS0, __expf(e1[u]) * iS1);
    __syncthreads();
    uint4* dst = (uint4*)(g_Ph + (((size_t)b * NIT + itile) * NKC + kc) * 2048);
    const uint4* src = (const uint4*)sp;
    dst[t] = src[t];
    dst[t + 256] = src[t + 256];
}

// ---------------------------------------------------------------------------
// K1b: vf_pack_h — v as fp16 pairs in m16n8k16 A-fragment order.
// ---------------------------------------------------------------------------
__global__ __launch_bounds__(256) void vf_pack_h_kernel() {
    int kc = blockIdx.x;     // 0..71
    int b  = blockIdx.y;
    const float* V = g_qkv + (size_t)b * NR * NNP + (size_t)(2 * ND) * NNP;
    __shared__ uint32_t sa[4096];
    int t = threadIdx.x;     // = channel row m
    const float* row = V + (size_t)t * NNP + kc * 32;
    float v[32];
#pragma unroll
    for (int u = 0; u < 8; u++) *(float4*)&v[u * 4] = *(const float4*)(row + u * 4);
    int mt = t >> 4;
    int lanebase = (t & 7) * 4;
    int madd = (t >> 3) & 1;
#pragma unroll
    for (int kp = 0; kp < 16; kp++) {
        uint32_t h = packh2(v[2 * kp], v[2 * kp + 1]);
        int idx = ((mt * 2 + (kp >> 3)) * 32 + lanebase + (kp & 3)) * 4 + madd + 2 * ((kp >> 2) & 1);
        sa[idx] = h;
    }
    __syncthreads();
    uint4* dst = (uint4*)(g_Vfh + ((size_t)b * NKC + kc) * 4096);
    const uint4* src = (const uint4*)sa;
#pragma unroll
    for (int u = 0; u < 4; u++) dst[t + u * 256] = src[t + u * 256];
}

// ---------------------------------------------------------------------------
// K4: out = gamma * (V @ P) + x  via mma.sync fp16, f32 accum.
// CTA: M=256 x N=128; K chunks of 32; 3-stage cp.async ring.
// 512 threads / 16 warps (64x32 warp tiles) for latency hiding (4 warps/SMSP).
// ---------------------------------------------------------------------------
#define ITERS NKC
#define S_STAGE 6144                    // uints per stage: A 4096 + B 2048
#define S_TOTAL3 (3 * S_STAGE * 4)      // 72 KB

__device__ __forceinline__ void og_prefetch(uint32_t* smem, const uint32_t* Vb, const uint32_t* Pb,
                                            int it, int slot, int tid) {
    uint32_t* sA = smem + slot * S_STAGE;
    uint32_t* sB = sA + 4096;
    const uint4* srcA = (const uint4*)(Vb + (size_t)it * 4096);
    const uint4* srcB = (const uint4*)(Pb + (size_t)it * 2048);
#pragma unroll
    for (int u = 0; u < 2; u++)
        cp_async16((uint4*)sA + tid + u * 512, srcA + tid + u * 512);
    cp_async16((uint4*)sB + tid, srcB + tid);
    CP_COMMIT();
}

__global__ __launch_bounds__(512, 1) void out_gemm_tc_kernel(const float* __restrict__ x,
                                                             const float* __restrict__ gamma,
                                                             float* __restrict__ out) {
    extern __shared__ uint32_t smem[];
    const int tid = threadIdx.x;
    const int lane = tid & 31;
    const int wid = tid >> 5;
    const int warp_m = wid & 3;        // 4 m-tiles of 64 rows
    const int warp_n = wid >> 2;       // 4 n-tiles of 32 cols

    const int itile = blockIdx.x;      // 0..17
    const int b = blockIdx.y;

    const uint32_t* Vb = g_Vfh + (size_t)b * NKC * 4096;
    const uint32_t* Pb = g_Ph + (((size_t)b * NIT + itile) * NKC) * 2048;

    float acc[4][4][4];
#pragma unroll
    for (int i = 0; i < 4; i++)
#pragma unroll
        for (int j = 0; j < 4; j++)
#pragma unroll
            for (int r = 0; r < 4; r++) acc[i][j][r] = 0.f;

    og_prefetch(smem, Vb, Pb, 0, 0, tid);
    og_prefetch(smem, Vb, Pb, 1, 1, tid);

    int slot = 0, nslot = 2;
    for (int it = 0; it < ITERS; it++) {
        if (it < ITERS - 1) { CP_WAIT(1); } else { CP_WAIT(0); }
        __syncthreads();
        if (it + 2 < ITERS) {
            og_prefetch(smem, Vb, Pb, it + 2, nslot, tid);
            if (++nslot == 3) nslot = 0;
        }

        const uint32_t* uA = smem + slot * S_STAGE;
        const uint32_t* uB = uA + 4096;
        if (++slot == 3) slot = 0;
#pragma unroll
        for (int ks = 0; ks < 2; ks++) {
            uint32_t a[4][4];
            uint32_t bfr[4][2];
#pragma unroll
            for (int i = 0; i < 4; i++) {
                int mt = warp_m * 4 + i;
                uint4 tdat = *(const uint4*)(uA + ((mt * 2 + ks) * 32 + lane) * 4);
                a[i][0] = tdat.x; a[i][1] = tdat.y; a[i][2] = tdat.z; a[i][3] = tdat.w;
            }
#pragma unroll
            for (int j = 0; j < 4; j++) {
                int nt = warp_n * 4 + j;
                uint2 tdat = *(const uint2*)(uB + ((nt * 2 + ks) * 32 + lane) * 2);
                bfr[j][0] = tdat.x; bfr[j][1] = tdat.y;
            }
#pragma unroll
            for (int i = 0; i < 4; i++)
#pragma unroll
                for (int j = 0; j < 4; j++)
                    mma_f16(acc[i][j], a[i], bfr[j]);
        }
    }

    // ---- epilogue: gamma*acc + x, float2 stores ----
    const float g = gamma[0];
    const float* xb = x + (size_t)b * NC * NNP;
    float* ob = out + (size_t)b * NC * NNP;
    const int gq = lane >> 2, tq = lane & 3;
#pragma unroll
    for (int i = 0; i < 4; i++) {
        int row0 = warp_m * 64 + i * 16 + gq;
#pragma unroll
        for (int j = 0; j < 4; j++) {
            int n = itile * 128 + warp_n * 32 + j * 8 + tq * 2;
            size_t o0 = (size_t)row0 * NNP + n;
            size_t o1 = o0 + (size_t)8 * NNP;
            float2 x0 = *(const float2*)(xb + o0);
            float2 x1 = *(const float2*)(xb + o1);
            float2 r0, r1;
            r0.x = g * acc[i][j][0] + x0.x;
            r0.y = g * acc[i][j][1] + x0.y;
            r1.x = g * acc[i][j][2] + x1.x;
            r1.y = g * acc[i][j][3] + x1.y;
            *(float2*)(ob + o0) = r0;
            *(float2*)(ob + o1) = r1;
        }
    }
}

// ---------------------------------------------------------------------------
extern "C" void kernel_launch(void* const* d_in, const int* in_sizes, int n_in,
                              void* d_out, int out_size) {
    const float* x     = (const float*)d_in[0];
    const float* Wq    = (const float*)d_in[1];
    const float* bq    = (const float*)d_in[2];
    const float* Wk    = (const float*)d_in[3];
    const float* bk    = (const float*)d_in[4];
    const float* Wv    = (const float*)d_in[5];
    const float* bv    = (const float*)d_in[6];
    const float* gamma = (const float*)d_in[7];
    float* out = (float*)d_out;

    pack_w_kernel<<<(NR * NC + 255) / 256, 256>>>(Wq, bq, Wk, bk, Wv, bv);

    dim3 g1(NNP / 64, NR / 64, NB);
    qkv_gemm_kernel<<<g1, 256>>>(x);

    dim3 gqk(NIT, 2, NB);
    qk_pack_kernel<<<gqk, 128>>>();

    dim3 g2(NIT, NIT, NB);
    energy_tc_kernel<<<g2, 256>>>();

    reduce_S_kernel<<<(NB * NNP + 255) / 256, 256>>>();

    dim3 gv(NKC, NB);
    vf_pack_h_kernel<<<gv, 256>>>();

    dim3 gp(NIT, NKC, NB);
    p_pack_h_kernel<<<gp, 256>>>();

    cudaFuncSetAttribute(out_gemm_tc_kernel, cudaFuncAttributeMaxDynamicSharedMemorySize, S_TOTAL3);
    dim3 g4(NIT, NB);
    out_gemm_tc_kernel<<<g4, 512, S_TOTAL3>>>(x, gamma, out);
}

// round 17
// speedup vs baseline: 1.7608x; 1.0814x over previous
#include <cuda_runtime.h>
#include <cuda_fp16.h>
#include <math.h>
#include <cstdint>

#define NB 16
#define NC 256
#define NNP 2304   // N = 48*48 pixels
#define ND 32      // d = C/8
#define NR 320     // packed qkv rows: 32 q + 32 k + 256 v
#define NKC 72     // k-chunks of 32 in NNP
#define NIT 18     // 128-pixel i-tiles in NNP

// ---- scratch (static device globals; no allocation at runtime) ----
__device__ float g_W[NR * NC];
__device__ float g_bias[NR];
__device__ float g_qkv[(size_t)NB * NR * NNP];            // 47 MB
__device__ float g_shift[NB * NNP];                       // per-key-row shift 3.2*||k_j||
__device__ float g_Spart[(size_t)NB * NNP * NIT];         // 2.7 MB, per-itile partial rowsums
__device__ float g_invS[NB * NNP];                        // 1 / sum_i exp(e - s_j)
__device__ uint32_t g_Ph[(size_t)NB * NIT * NKC * 2048];  // 170 MB, fp16 frag-ordered exp(e-s_j)
__device__ uint32_t g_Vfh[(size_t)NB * NKC * 4096];       // 19 MB, fp16 frag-ordered v*invS*16
__device__ uint32_t g_Kfh[(size_t)NB * NIT * 2048];       // 2.4 MB, fp16 A-fragment k (per j-tile)
__device__ uint32_t g_Qfh[(size_t)NB * NIT * 2048];       // 2.4 MB, fp16 B-fragment q (per i-tile)

__device__ __forceinline__ uint32_t packh2(float lo, float hi) {
    __half2 h = __floats2half2_rn(lo, hi);
    return *reinterpret_cast<uint32_t*>(&h);
}
__device__ __forceinline__ void mma_f16(float* c, const uint32_t* a, const uint32_t* b) {
    asm volatile(
        "mma.sync.aligned.m16n8k16.row.col.f32.f16.f16.f32 "
        "{%0,%1,%2,%3}, {%4,%5,%6,%7}, {%8,%9}, {%0,%1,%2,%3};"
        : "+f"(c[0]), "+f"(c[1]), "+f"(c[2]), "+f"(c[3])
        : "r"(a[0]), "r"(a[1]), "r"(a[2]), "r"(a[3]), "r"(b[0]), "r"(b[1]));
}
__device__ __forceinline__ void cp_async16(void* smem_dst, const void* gmem_src) {
    uint32_t sa = (uint32_t)__cvta_generic_to_shared(smem_dst);
    asm volatile("cp.async.cg.shared.global [%0], [%1], 16;" :: "r"(sa), "l"(gmem_src));
}
#define CP_COMMIT() asm volatile("cp.async.commit_group;" ::: "memory")
#define CP_WAIT(n)  asm volatile("cp.async.wait_group %0;" :: "n"(n) : "memory")

// ---------------------------------------------------------------------------
// K0: pack weights + biases
// ---------------------------------------------------------------------------
__global__ void pack_w_kernel(const float* __restrict__ Wq, const float* __restrict__ bq,
                              const float* __restrict__ Wk, const float* __restrict__ bk,
                              const float* __restrict__ Wv, const float* __restrict__ bv) {
    int idx = blockIdx.x * blockDim.x + threadIdx.x;
    if (idx < NR * NC) {
        int r = idx / NC, c = idx - r * NC;
        float v;
        if (r < ND)          v = Wq[r * NC + c];
        else if (r < 2 * ND) v = Wk[(r - ND) * NC + c];
        else                 v = Wv[(r - 2 * ND) * NC + c];
        g_W[idx] = v;
    }
    if (idx < NR) {
        float v;
        if (idx < ND)          v = bq[idx];
        else if (idx < 2 * ND) v = bk[idx - ND];
        else                   v = bv[idx - 2 * ND];
        g_bias[idx] = v;
    }
}

// ---------------------------------------------------------------------------
// K1: qkv projection GEMM (fp32 SIMT)
// ---------------------------------------------------------------------------
__global__ __launch_bounds__(256) void qkv_gemm_kernel(const float* __restrict__ x) {
    int b = blockIdx.z;
    int m0 = blockIdx.y * 64;
    int n0 = blockIdx.x * 64;
    const float* A  = g_W;
    const float* Bm = x + (size_t)b * NC * NNP;
    float* Cm = g_qkv + (size_t)b * NR * NNP;

    __shared__ float As[16][64];
    __shared__ float Bs[16][64];
    int tid = threadIdx.x;
    int tx = tid & 15, ty = tid >> 4;
    float acc[4][4] = {};

    for (int k0 = 0; k0 < NC; k0 += 16) {
        int ar = tid >> 2, ac = (tid & 3) * 4;
        float4 av = *(const float4*)(A + (size_t)(m0 + ar) * NC + k0 + ac);
        As[ac + 0][ar] = av.x; As[ac + 1][ar] = av.y;
        As[ac + 2][ar] = av.z; As[ac + 3][ar] = av.w;
        int br = tid >> 4, bc = (tid & 15) * 4;
        *(float4*)&Bs[br][bc] = *(const float4*)(Bm + (size_t)(k0 + br) * NNP + n0 + bc);
        __syncthreads();
#pragma unroll
        for (int kk = 0; kk < 16; kk++) {
            float a[4], bb[4];
            *(float4*)a  = *(const float4*)&As[kk][ty * 4];
            *(float4*)bb = *(const float4*)&Bs[kk][tx * 4];
#pragma unroll
            for (int i = 0; i < 4; i++)
#pragma unroll
                for (int j = 0; j < 4; j++)
                    acc[i][j] += a[i] * bb[j];
        }
        __syncthreads();
    }
#pragma unroll
    for (int i = 0; i < 4; i++) {
        int m = m0 + ty * 4 + i;
        float bias = g_bias[m];
        float4 o;
        o.x = acc[i][0] + bias; o.y = acc[i][1] + bias;
        o.z = acc[i][2] + bias; o.w = acc[i][3] + bias;
        *(float4*)(Cm + (size_t)m * NNP + n0 + tx * 4) = o;
    }
}

// ---------------------------------------------------------------------------
// K1c: qk_pack — q and k as fp16 pairs in mma fragment order, per 128-tile.
// which=0 (k) additionally computes the per-row shift s_j = 3.2*||k_j||.
// ---------------------------------------------------------------------------
__global__ __launch_bounds__(128) void qk_pack_kernel() {
    int tile  = blockIdx.x;    // 0..17
    int which = blockIdx.y;    // 0=k, 1=q
    int b     = blockIdx.z;
    const float* src = g_qkv + (size_t)b * NR * NNP + (which ? 0 : (size_t)ND * NNP);
    uint32_t* dst = (which ? g_Qfh : g_Kfh) + ((size_t)b * NIT + tile) * 2048;

    __shared__ float st[32][132];
    __shared__ uint32_t sp[2048];
    int t = threadIdx.x;       // 0..127
    int j0 = tile * 128;
#pragma unroll
    for (int d = 0; d < 32; d++)
        st[d][t] = src[(size_t)d * NNP + j0 + t];
    __syncthreads();

    float v[32];
#pragma unroll
    for (int d = 0; d < 32; d++) v[d] = st[d][t];

    if (which == 0) {
        // per-row shift from ||k_j||
        float nrm2 = 0.f;
#pragma unroll
        for (int d = 0; d < 32; d++) nrm2 += v[d] * v[d];
        g_shift[b * NNP + j0 + t] = 3.2f * sqrtf(nrm2);

        int mt = t >> 4;
        int lanebase = (t & 7) * 4;
        int madd = (t >> 3) & 1;
#pragma unroll
        for (int kp = 0; kp < 16; kp++) {
            uint32_t h = packh2(v[2 * kp], v[2 * kp + 1]);
            int idx = ((mt * 2 + (kp >> 3)) * 32 + lanebase + (kp & 3)) * 4 + madd + 2 * ((kp >> 2) & 1);
            sp[idx] = h;
        }
    } else {
        int nt = t >> 3;
        int lanebase = (t & 7) * 4;
#pragma unroll
        for (int kp = 0; kp < 16; kp++) {
            uint32_t h = packh2(v[2 * kp], v[2 * kp + 1]);
            int idx = ((nt * 2 + (kp >> 3)) * 32 + lanebase + (kp & 3)) * 2 + ((kp >> 2) & 1);
            sp[idx] = h;
        }
    }
    __syncthreads();
    uint4* d4 = (uint4*)dst;
    const uint4* s4 = (const uint4*)sp;
#pragma unroll
    for (int u = 0; u < 4; u++) d4[t + u * 128] = s4[t + u * 128];
}

// ---------------------------------------------------------------------------
// K2: energy via fp16 mma, fused softmax-numerator production.
// e = k_j . q_i for a 128j x 128i tile; directly emits P-fragments
// exp(e - s_j) fp16 (clamped at 60000) in m16n8k16 B-fragment order, plus
// deterministic per-row partial sums with the SAME shift. No E, no p_pack.
// ---------------------------------------------------------------------------
__global__ __launch_bounds__(256) void energy_tc_kernel() {
    int it = blockIdx.x;      // i-tile 0..17
    int jt = blockIdx.y;      // j-tile 0..17
    int b  = blockIdx.z;

    __shared__ uint32_t sm[4096];          // A 2048 + B 2048
    __shared__ float stf[32][129];         // chunk staging (32j x 128i)
    __shared__ uint32_t frag[2048];        // fragment staging for one kc block
    __shared__ float ssum[32][17];         // rowsum partials
    __shared__ float sshift[128];          // per-row shifts for this j-tile
    uint32_t* sA = sm;
    uint32_t* sB = sm + 2048;
    const uint32_t* srcA = g_Kfh + ((size_t)b * NIT + jt) * 2048;
    const uint32_t* srcB = g_Qfh + ((size_t)b * NIT + it) * 2048;
    int tid = threadIdx.x;
#pragma unroll
    for (int u = 0; u < 2; u++) {
        cp_async16((uint4*)sA + tid + u * 256, (const uint4*)srcA + tid + u * 256);
        cp_async16((uint4*)sB + tid + u * 256, (const uint4*)srcB + tid + u * 256);
    }
    CP_COMMIT();
    if (tid < 128) sshift[tid] = g_shift[b * NNP + jt * 128 + tid];

    const int lane = tid & 31;
    const int wid = tid >> 5;
    const int warp_m = wid & 1;    // 2 x 64 j
    const int warp_n = wid >> 1;   // 4 x 32 i
    const int gq = lane >> 2, tq = lane & 3;

    float acc[4][4][4];
#pragma unroll
    for (int i = 0; i < 4; i++)
#pragma unroll
        for (int j = 0; j < 4; j++)
#pragma unroll
            for (int r = 0; r < 4; r++) acc[i][j][r] = 0.f;

    CP_WAIT(0);
    __syncthreads();

#pragma unroll
    for (int ks = 0; ks < 2; ks++) {
        uint32_t a[4][4], bfr[4][2];
#pragma unroll
        for (int i = 0; i < 4; i++) {
            int mt = warp_m * 4 + i;
            uint4 tdat = *(const uint4*)(sA + ((mt * 2 + ks) * 32 + lane) * 4);
            a[i][0] = tdat.x; a[i][1] = tdat.y; a[i][2] = tdat.z; a[i][3] = tdat.w;
        }
#pragma unroll
        for (int j = 0; j < 4; j++) {
            int nt = warp_n * 4 + j;
            uint2 tdat = *(const uint2*)(sB + ((nt * 2 + ks) * 32 + lane) * 2);
            bfr[j][0] = tdat.x; bfr[j][1] = tdat.y;
        }
#pragma unroll
        for (int i = 0; i < 4; i++)
#pragma unroll
            for (int j = 0; j < 4; j++)
                mma_f16(acc[i][j], a[i], bfr[j]);
    }
    __syncthreads();

    // ---- epilogue: 4 chunks of 32 j-rows -> exp fragments + rowsums ----
    const int kp = tid & 15, nb = tid >> 4;
    const int k0 = kp * 2;
    const int ksf = kp >> 3, rg = (kp >> 2) & 1, kl = kp & 3;
    const int fbase = ((nb * 2 + ksf) * 32 + kl) * 2 + rg;

    for (int c = 0; c < 4; c++) {
        if (warp_m == (c >> 1)) {
            int coff = (c & 1) * 2;
#pragma unroll
            for (int ii = 0; ii < 2; ii++)
#pragma unroll
                for (int jj = 0; jj < 4; jj++) {
                    int col = warp_n * 32 + jj * 8 + tq * 2;
                    int r0 = ii * 16 + gq;
                    stf[r0][col]     = acc[coff + ii][jj][0];
                    stf[r0][col + 1] = acc[coff + ii][jj][1];
                    stf[r0 + 8][col]     = acc[coff + ii][jj][2];
                    stf[r0 + 8][col + 1] = acc[coff + ii][jj][3];
                }
        }
        __syncthreads();

        float sh0 = sshift[c * 32 + k0];
        float sh1 = sshift[c * 32 + k0 + 1];
        float rs0 = 0.f, rs1 = 0.f;
#pragma unroll
        for (int u = 0; u < 8; u++) {
            float x0 = fminf(__expf(stf[k0][nb * 8 + u] - sh0), 60000.f);
            float x1 = fminf(__expf(stf[k0 + 1][nb * 8 + u] - sh1), 60000.f);
            frag[fbase + u * 8] = packh2(x0, x1);
            rs0 += x0; rs1 += x1;
        }
        ssum[k0][nb] = rs0;
        ssum[k0 + 1][nb] = rs1;
        __syncthreads();

        uint4* dst = (uint4*)(g_Ph + (((size_t)b * NIT + it) * NKC + (jt * 4 + c)) * 2048);
        const uint4* src = (const uint4*)frag;
        dst[tid] = src[tid];
        dst[tid + 256] = src[tid + 256];

        if (tid < 32) {
            float s = 0.f;
#pragma unroll
            for (int n2 = 0; n2 < 16; n2++) s += ssum[tid][n2];
            g_Spart[((size_t)b * NNP + jt * 128 + c * 32 + tid) * NIT + it] = s;
        }
        __syncthreads();
    }
}

// ---------------------------------------------------------------------------
// K2b: reduce partials -> invS = 1 / sum_i exp(e - s_j)
// ---------------------------------------------------------------------------
__global__ __launch_bounds__(256) void reduce_S_kernel() {
    int idx = blockIdx.x * blockDim.x + threadIdx.x;
    if (idx < NB * NNP) {
        const float* p = g_Spart + (size_t)idx * NIT;
        float s = 0.f;
#pragma unroll
        for (int u = 0; u < NIT; u++) s += p[u];
        g_invS[idx] = 1.0f / s;
    }
}

// ---------------------------------------------------------------------------
// K1b: vf_pack_h — V' = v * invS * 16 as fp16 pairs in A-fragment order.
// ---------------------------------------------------------------------------
__global__ __launch_bounds__(256) void vf_pack_h_kernel() {
    int kc = blockIdx.x;     // 0..71
    int b  = blockIdx.y;
    const float* V = g_qkv + (size_t)b * NR * NNP + (size_t)(2 * ND) * NNP;
    __shared__ uint32_t sa[4096];
    __shared__ float sInv[32];
    int t = threadIdx.x;     // = channel row m
    if (t < 32) sInv[t] = g_invS[b * NNP + kc * 32 + t] * 16.0f;
    __syncthreads();
    const float* row = V + (size_t)t * NNP + kc * 32;
    float v[32];
#pragma unroll
    for (int u = 0; u < 8; u++) *(float4*)&v[u * 4] = *(const float4*)(row + u * 4);
    int mt = t >> 4;
    int lanebase = (t & 7) * 4;
    int madd = (t >> 3) & 1;
#pragma unroll
    for (int kp = 0; kp < 16; kp++) {
        uint32_t h = packh2(v[2 * kp] * sInv[2 * kp], v[2 * kp + 1] * sInv[2 * kp + 1]);
        int idx = ((mt * 2 + (kp >> 3)) * 32 + lanebase + (kp & 3)) * 4 + madd + 2 * ((kp >> 2) & 1);
        sa[idx] = h;
    }
    __syncthreads();
    uint4* dst = (uint4*)(g_Vfh + ((size_t)b * NKC + kc) * 4096);
    const uint4* src = (const uint4*)sa;
#pragma unroll
    for (int u = 0; u < 4; u++) dst[t + u * 256] = src[t + u * 256];
}

// ---------------------------------------------------------------------------
// K4: out = (gamma/16) * (V' @ P) + x  via mma.sync fp16, f32 accum.
// CTA: M=256 x N=128; K chunks of 32; 3-stage cp.async ring; 512 threads.
// ---------------------------------------------------------------------------
#define ITERS NKC
#define S_STAGE 6144                    // uints per stage: A 4096 + B 2048
#define S_TOTAL3 (3 * S_STAGE * 4)      // 72 KB

__device__ __forceinline__ void og_prefetch(uint32_t* smem, const uint32_t* Vb, const uint32_t* Pb,
                                            int it, int slot, int tid) {
    uint32_t* sA = smem + slot * S_STAGE;
    uint32_t* sB = sA + 4096;
    const uint4* srcA = (const uint4*)(Vb + (size_t)it * 4096);
    const uint4* srcB = (const uint4*)(Pb + (size_t)it * 2048);
#pragma unroll
    for (int u = 0; u < 2; u++)
        cp_async16((uint4*)sA + tid + u * 512, srcA + tid + u * 512);
    cp_async16((uint4*)sB + tid, srcB + tid);
    CP_COMMIT();
}

__global__ __launch_bounds__(512, 1) void out_gemm_tc_kernel(const float* __restrict__ x,
                                                             const float* __restrict__ gamma,
                                                             float* __restrict__ out) {
    extern __shared__ uint32_t smem[];
    const int tid = threadIdx.x;
    const int lane = tid & 31;
    const int wid = tid >> 5;
    const int warp_m = wid & 3;        // 4 m-tiles of 64 rows
    const int warp_n = wid >> 2;       // 4 n-tiles of 32 cols

    const int itile = blockIdx.x;      // 0..17
    const int b = blockIdx.y;

    const uint32_t* Vb = g_Vfh + (size_t)b * NKC * 4096;
    const uint32_t* Pb = g_Ph + (((size_t)b * NIT + itile) * NKC) * 2048;

    float acc[4][4][4];
#pragma unroll
    for (int i = 0; i < 4; i++)
#pragma unroll
        for (int j = 0; j < 4; j++)
#pragma unroll
            for (int r = 0; r < 4; r++) acc[i][j][r] = 0.f;

    og_prefetch(smem, Vb, Pb, 0, 0, tid);
    og_prefetch(smem, Vb, Pb, 1, 1, tid);

    int slot = 0, nslot = 2;
    for (int it = 0; it < ITERS; it++) {
        if (it < ITERS - 1) { CP_WAIT(1); } else { CP_WAIT(0); }
        __syncthreads();
        if (it + 2 < ITERS) {
            og_prefetch(smem, Vb, Pb, it + 2, nslot, tid);
            if (++nslot == 3) nslot = 0;
        }

        const uint32_t* uA = smem + slot * S_STAGE;
        const uint32_t* uB = uA + 4096;
        if (++slot == 3) slot = 0;
#pragma unroll
        for (int ks = 0; ks < 2; ks++) {
            uint32_t a[4][4];
            uint32_t bfr[4][2];
#pragma unroll
            for (int i = 0; i < 4; i++) {
                int mt = warp_m * 4 + i;
                uint4 tdat = *(const uint4*)(uA + ((mt * 2 + ks) * 32 + lane) * 4);
                a[i][0] = tdat.x; a[i][1] = tdat.y; a[i][2] = tdat.z; a[i][3] = tdat.w;
            }
#pragma unroll
            for (int j = 0; j < 4; j++) {
                int nt = warp_n * 4 + j;
                uint2 tdat = *(const uint2*)(uB + ((nt * 2 + ks) * 32 + lane) * 2);
                bfr[j][0] = tdat.x; bfr[j][1] = tdat.y;
            }
#pragma unroll
            for (int i = 0; i < 4; i++)
#pragma unroll
                for (int j = 0; j < 4; j++)
                    mma_f16(acc[i][j], a[i], bfr[j]);
        }
    }

    // ---- epilogue: (gamma/16)*acc + x, float2 stores ----
    const float g = gamma[0] * 0.0625f;
    const float* xb = x + (size_t)b * NC * NNP;
    float* ob = out + (size_t)b * NC * NNP;
    const int gq = lane >> 2, tq = lane & 3;
#pragma unroll
    for (int i = 0; i < 4; i++) {
        int row0 = warp_m * 64 + i * 16 + gq;
#pragma unroll
        for (int j = 0; j < 4; j++) {
            int n = itile * 128 + warp_n * 32 + j * 8 + tq * 2;
            size_t o0 = (size_t)row0 * NNP + n;
            size_t o1 = o0 + (size_t)8 * NNP;
            float2 x0 = *(const float2*)(xb + o0);
            float2 x1 = *(const float2*)(xb + o1);
            float2 r0, r1;
            r0.x = g * acc[i][j][0] + x0.x;
            r0.y = g * acc[i][j][1] + x0.y;
            r1.x = g * acc[i][j][2] + x1.x;
            r1.y = g * acc[i][j][3] + x1.y;
            *(float2*)(ob + o0) = r0;
            *(float2*)(ob + o1) = r1;
        }
    }
}

// ---------------------------------------------------------------------------
extern "C" void kernel_launch(void* const* d_in, const int* in_sizes, int n_in,
                              void* d_out, int out_size) {
    const float* x     = (const float*)d_in[0];
    const float* Wq    = (const float*)d_in[1];
    const float* bq    = (const float*)d_in[2];
    const float* Wk    = (const float*)d_in[3];
    const float* bk    = (const float*)d_in[4];
    const float* Wv    = (const float*)d_in[5];
    const float* bv    = (const float*)d_in[6];
    const float* gamma = (const float*)d_in[7];
    float* out = (float*)d_out;

    pack_w_kernel<<<(NR * NC + 255) / 256, 256>>>(Wq, bq, Wk, bk, Wv, bv);

    dim3 g1(NNP / 64, NR / 64, NB);
    qkv_gemm_kernel<<<g1, 256>>>(x);

    dim3 gqk(NIT, 2, NB);
    qk_pack_kernel<<<gqk, 128>>>();

    dim3 g2(NIT, NIT, NB);
    energy_tc_kernel<<<g2, 256>>>();

    reduce_S_kernel<<<(NB * NNP + 255) / 256, 256>>>();

    dim3 gv(NKC, NB);
    vf_pack_h_kernel<<<gv, 256>>>();

    cudaFuncSetAttribute(out_gemm_tc_kernel, cudaFuncAttributeMaxDynamicSharedMemorySize, S_TOTAL3);
    dim3 g4(NIT, NB);
    out_gemm_tc_kernel<<<g4, 512, S_TOTAL3>>>(x, gamma, out);
}